// round 1
// baseline (speedup 1.0000x reference)
#include <cuda_runtime.h>
#include <math.h>

// ---------------------------------------------------------------------------
// InteractionLayer: cross-attention det->rel
//   det_q = det_in @ W_det^T + b_det        [B][Nd][F]
//   rel_k = rel_in @ W_rel^T + b_rel        [B][Nr][F]
//   det_v = det_in @ W_val^T + b_val        [B][Nd][F]
//   scores[b][r][d] = <rel_k[b][r], det_q[b][d]> / sqrt(F)
//   w = softmax_d(scores)
//   rel_add[b][r][f] = sum_d w[b][r][d] * det_v[b][d][f]
//   out_rel[r][b][:] = LN(rel_add[b][r][:] + rel_in[r][b][:]) * gamma + beta
//   out = concat(det_in, out_rel)
// Shapes: Nd=Nr=2048, B=8, D=F=512
// ---------------------------------------------------------------------------

#define ND 2048
#define NR 2048
#define NB 8
#define DM 512
#define DF 512

#define BM 128
#define BN 128
#define BK 8
#define TM 8
#define TN 8

// scratch (no cudaMalloc allowed)
__device__ float g_q[(size_t)NB * ND * DF];     // det_q, later reused as rel_add
__device__ float g_k[(size_t)NB * NR * DF];     // rel_k
__device__ float g_v[(size_t)NB * ND * DF];     // det_v
__device__ float g_s[(size_t)NB * NR * ND];     // scores / softmax weights

// ---------------------------------------------------------------------------
// C[m,n] = alpha * sum_k A[m*lda+k] * B[n*ldb+k] + bias[n]   (NT: both K-major)
// Tiles: 128x128x8, 256 threads, 8x8 per-thread microtile. All dims divide tiles.
// ---------------------------------------------------------------------------
__global__ __launch_bounds__(256) void gemm_nt(
    const float* __restrict__ A, const float* __restrict__ B, float* __restrict__ C,
    int K, long lda, long ldb, long ldc,
    long strideA, long strideB, long strideC,
    float alpha, const float* __restrict__ bias)
{
    const int bz = blockIdx.z;
    A += (long)bz * strideA;
    B += (long)bz * strideB;
    C += (long)bz * strideC;

    __shared__ float As[BK][BM];
    __shared__ float Bs[BK][BN];

    const int tid = threadIdx.x;
    const int rowBase = blockIdx.x * BM;
    const int colBase = blockIdx.y * BN;

    const int trow = (tid / 16) * TM;
    const int tcol = (tid % 16) * TN;

    const int lr = tid >> 1;        // 0..127 (tile row)
    const int lk = (tid & 1) * 4;   // 0 or 4 (k quad)

    float acc[TM][TN];
    #pragma unroll
    for (int i = 0; i < TM; i++)
        #pragma unroll
        for (int j = 0; j < TN; j++) acc[i][j] = 0.f;

    for (int kt = 0; kt < K; kt += BK) {
        float4 av = *reinterpret_cast<const float4*>(&A[(long)(rowBase + lr) * lda + kt + lk]);
        float4 bv = *reinterpret_cast<const float4*>(&B[(long)(colBase + lr) * ldb + kt + lk]);
        As[lk + 0][lr] = av.x; As[lk + 1][lr] = av.y; As[lk + 2][lr] = av.z; As[lk + 3][lr] = av.w;
        Bs[lk + 0][lr] = bv.x; Bs[lk + 1][lr] = bv.y; Bs[lk + 2][lr] = bv.z; Bs[lk + 3][lr] = bv.w;
        __syncthreads();
        #pragma unroll
        for (int kk = 0; kk < BK; kk++) {
            float a[TM], b[TN];
            #pragma unroll
            for (int i = 0; i < TM; i++) a[i] = As[kk][trow + i];
            #pragma unroll
            for (int j = 0; j < TN; j++) b[j] = Bs[kk][tcol + j];
            #pragma unroll
            for (int i = 0; i < TM; i++)
                #pragma unroll
                for (int j = 0; j < TN; j++)
                    acc[i][j] = fmaf(a[i], b[j], acc[i][j]);
        }
        __syncthreads();
    }

    #pragma unroll
    for (int i = 0; i < TM; i++) {
        const long crow = rowBase + trow + i;
        #pragma unroll
        for (int j = 0; j < TN; j += 4) {
            const int cc = colBase + tcol + j;
            float4 v;
            v.x = alpha * acc[i][j + 0];
            v.y = alpha * acc[i][j + 1];
            v.z = alpha * acc[i][j + 2];
            v.w = alpha * acc[i][j + 3];
            if (bias) {
                v.x += bias[cc + 0]; v.y += bias[cc + 1];
                v.z += bias[cc + 2]; v.w += bias[cc + 3];
            }
            *reinterpret_cast<float4*>(&C[crow * ldc + cc]) = v;
        }
    }
}

// ---------------------------------------------------------------------------
// C[m,n] = sum_k A[m*lda+k] * B[k*ldb+n]   (NN: A K-major, B N-major)
// ---------------------------------------------------------------------------
__global__ __launch_bounds__(256) void gemm_nn(
    const float* __restrict__ A, const float* __restrict__ B, float* __restrict__ C,
    int K, long lda, long ldb, long ldc,
    long strideA, long strideB, long strideC)
{
    const int bz = blockIdx.z;
    A += (long)bz * strideA;
    B += (long)bz * strideB;
    C += (long)bz * strideC;

    __shared__ float As[BK][BM];
    __shared__ float Bs[BK][BN];

    const int tid = threadIdx.x;
    const int rowBase = blockIdx.x * BM;
    const int colBase = blockIdx.y * BN;

    const int trow = (tid / 16) * TM;
    const int tcol = (tid % 16) * TN;

    const int lr = tid >> 1;
    const int lk = (tid & 1) * 4;

    const int bk = tid >> 5;        // 0..7
    const int bn = (tid & 31) * 4;  // 0..124

    float acc[TM][TN];
    #pragma unroll
    for (int i = 0; i < TM; i++)
        #pragma unroll
        for (int j = 0; j < TN; j++) acc[i][j] = 0.f;

    for (int kt = 0; kt < K; kt += BK) {
        float4 av = *reinterpret_cast<const float4*>(&A[(long)(rowBase + lr) * lda + kt + lk]);
        float4 bv = *reinterpret_cast<const float4*>(&B[(long)(kt + bk) * ldb + colBase + bn]);
        As[lk + 0][lr] = av.x; As[lk + 1][lr] = av.y; As[lk + 2][lr] = av.z; As[lk + 3][lr] = av.w;
        *reinterpret_cast<float4*>(&Bs[bk][bn]) = bv;
        __syncthreads();
        #pragma unroll
        for (int kk = 0; kk < BK; kk++) {
            float a[TM], b[TN];
            #pragma unroll
            for (int i = 0; i < TM; i++) a[i] = As[kk][trow + i];
            #pragma unroll
            for (int j = 0; j < TN; j++) b[j] = Bs[kk][tcol + j];
            #pragma unroll
            for (int i = 0; i < TM; i++)
                #pragma unroll
                for (int j = 0; j < TN; j++)
                    acc[i][j] = fmaf(a[i], b[j], acc[i][j]);
        }
        __syncthreads();
    }

    #pragma unroll
    for (int i = 0; i < TM; i++) {
        const long crow = rowBase + trow + i;
        #pragma unroll
        for (int j = 0; j < TN; j += 4) {
            const int cc = colBase + tcol + j;
            float4 v;
            v.x = acc[i][j + 0]; v.y = acc[i][j + 1];
            v.z = acc[i][j + 2]; v.w = acc[i][j + 3];
            *reinterpret_cast<float4*>(&C[crow * ldc + cc]) = v;
        }
    }
}

// ---------------------------------------------------------------------------
// In-place softmax over each row of length `cols` (cols = 2048, multiple of 1024)
// ---------------------------------------------------------------------------
__global__ __launch_bounds__(256) void softmax_rows(float* __restrict__ S, int cols)
{
    float* p = S + (long)blockIdx.x * cols;
    const int tid = threadIdx.x;
    __shared__ float red[256];

    float m = -INFINITY;
    for (int c = tid * 4; c < cols; c += 1024) {
        float4 v = *reinterpret_cast<const float4*>(&p[c]);
        m = fmaxf(m, fmaxf(fmaxf(v.x, v.y), fmaxf(v.z, v.w)));
    }
    red[tid] = m; __syncthreads();
    for (int s = 128; s > 0; s >>= 1) {
        if (tid < s) red[tid] = fmaxf(red[tid], red[tid + s]);
        __syncthreads();
    }
    m = red[0];
    __syncthreads();

    float sum = 0.f;
    for (int c = tid * 4; c < cols; c += 1024) {
        float4 v = *reinterpret_cast<const float4*>(&p[c]);
        v.x = __expf(v.x - m); v.y = __expf(v.y - m);
        v.z = __expf(v.z - m); v.w = __expf(v.w - m);
        *reinterpret_cast<float4*>(&p[c]) = v;
        sum += v.x + v.y + v.z + v.w;
    }
    red[tid] = sum; __syncthreads();
    for (int s = 128; s > 0; s >>= 1) {
        if (tid < s) red[tid] += red[tid + s];
        __syncthreads();
    }
    const float inv = 1.f / red[0];

    for (int c = tid * 4; c < cols; c += 1024) {
        float4 v = *reinterpret_cast<const float4*>(&p[c]);
        v.x *= inv; v.y *= inv; v.z *= inv; v.w *= inv;
        *reinterpret_cast<float4*>(&p[c]) = v;
    }
}

// ---------------------------------------------------------------------------
// out[r][b][:] = LN(add[b][r][:] + rel_in[r][b][:]) * gamma + beta
// One 128-thread block per (b,r), 4 floats/thread (DM=512).
// ---------------------------------------------------------------------------
__global__ __launch_bounds__(128) void residual_ln(
    const float* __restrict__ add, const float* __restrict__ rel_in,
    const float* __restrict__ gamma, const float* __restrict__ beta,
    float* __restrict__ out)
{
    const long idx = blockIdx.x;          // b*NR + r
    const long b = idx >> 11;             // /2048
    const long r = idx & 2047;
    const int tid = threadIdx.x;
    const int f = tid * 4;

    const float4 a4 = *reinterpret_cast<const float4*>(&add[idx * DM + f]);
    const float4 r4 = *reinterpret_cast<const float4*>(&rel_in[(r * NB + b) * DM + f]);
    float x0 = a4.x + r4.x, x1 = a4.y + r4.y, x2 = a4.z + r4.z, x3 = a4.w + r4.w;

    float sum = x0 + x1 + x2 + x3;
    float ssq = x0 * x0 + x1 * x1 + x2 * x2 + x3 * x3;
    #pragma unroll
    for (int o = 16; o > 0; o >>= 1) {
        sum += __shfl_xor_sync(0xFFFFFFFFu, sum, o);
        ssq += __shfl_xor_sync(0xFFFFFFFFu, ssq, o);
    }
    __shared__ float s1[4], s2[4];
    const int w = tid >> 5;
    if ((tid & 31) == 0) { s1[w] = sum; s2[w] = ssq; }
    __syncthreads();
    sum = s1[0] + s1[1] + s1[2] + s1[3];
    ssq = s2[0] + s2[1] + s2[2] + s2[3];

    const float mean = sum * (1.f / DM);
    const float var = ssq * (1.f / DM) - mean * mean;
    const float rstd = rsqrtf(var + 1e-5f);

    const float4 g4 = *reinterpret_cast<const float4*>(&gamma[f]);
    const float4 be4 = *reinterpret_cast<const float4*>(&beta[f]);
    float4 o4;
    o4.x = (x0 - mean) * rstd * g4.x + be4.x;
    o4.y = (x1 - mean) * rstd * g4.y + be4.y;
    o4.z = (x2 - mean) * rstd * g4.z + be4.z;
    o4.w = (x3 - mean) * rstd * g4.w + be4.w;
    *reinterpret_cast<float4*>(&out[(r * NB + b) * DM + f]) = o4;
}

// ---------------------------------------------------------------------------
extern "C" void kernel_launch(void* const* d_in, const int* in_sizes, int n_in,
                              void* d_out, int out_size)
{
    const float* det_in = (const float*)d_in[0];
    const float* rel_in = (const float*)d_in[1];
    const float* W_det  = (const float*)d_in[2];
    const float* b_det  = (const float*)d_in[3];
    const float* W_rel  = (const float*)d_in[4];
    const float* b_rel  = (const float*)d_in[5];
    const float* W_val  = (const float*)d_in[6];
    const float* b_val  = (const float*)d_in[7];
    const float* gamma  = (const float*)d_in[8];
    const float* beta   = (const float*)d_in[9];
    float* out = (float*)d_out;

    float *q, *k, *v, *s;
    cudaGetSymbolAddress((void**)&q, g_q);
    cudaGetSymbolAddress((void**)&k, g_k);
    cudaGetSymbolAddress((void**)&v, g_v);
    cudaGetSymbolAddress((void**)&s, g_s);

    // Pass-through: out[0 : Nd*B*D] = det_in
    cudaMemcpyAsync(out, det_in, (size_t)ND * NB * DM * sizeof(float),
                    cudaMemcpyDeviceToDevice);

    dim3 blk(256);

    // --- projections: per batch b, A = in[:, b, :] (lda = B*D), C = [b][n][f]
    dim3 gp(ND / BM, DF / BN, NB);
    gemm_nt<<<gp, blk>>>(det_in, W_det, q, DM, (long)NB * DM, DM, DF,
                         DM, 0, (long)ND * DF, 1.f, b_det);
    gemm_nt<<<gp, blk>>>(rel_in, W_rel, k, DM, (long)NB * DM, DM, DF,
                         DM, 0, (long)NR * DF, 1.f, b_rel);
    gemm_nt<<<gp, blk>>>(det_in, W_val, v, DM, (long)NB * DM, DM, DF,
                         DM, 0, (long)ND * DF, 1.f, b_val);

    // --- scores[b][r][d] = <rel_k[b][r], det_q[b][d]> / sqrt(F)
    const float inv_sqrt_f = 1.f / sqrtf((float)DF);
    dim3 gs(NR / BM, ND / BN, NB);
    gemm_nt<<<gs, blk>>>(k, q, s, DF, DF, DF, ND,
                         (long)NR * DF, (long)ND * DF, (long)NR * ND,
                         inv_sqrt_f, nullptr);

    // --- softmax over det axis (rows of 2048)
    softmax_rows<<<NB * NR, 256>>>(s, ND);

    // --- rel_add[b][r][f] = sum_d w[b][r][d] * det_v[b][d][f]   (reuse q)
    dim3 ga(NR / BM, DF / BN, NB);
    gemm_nn<<<ga, blk>>>(s, v, q, ND, ND, DF, DF,
                         (long)NR * ND, (long)ND * DF, (long)NR * DF);

    // --- residual + LayerNorm -> out[Nd*B*D + ...]
    residual_ln<<<NB * NR, 128>>>(q, rel_in, gamma, beta,
                                  out + (size_t)ND * NB * DM);
}

// round 3
// speedup vs baseline: 2.7629x; 2.7629x over previous
#include <cuda_runtime.h>
#include <cstdint>
#include <math.h>

// ---------------------------------------------------------------------------
// InteractionLayer via tf32 mma.sync (arch-portable PTX; harness targets
// plain sm_103 so tcgen05/'a'-features are unavailable).
//   det_q = det_in @ W_det^T + b_det        [B][Nd][F]
//   rel_k = rel_in @ W_rel^T + b_rel        [B][Nr][F]
//   det_v = det_in @ W_val^T + b_val        [B][Nd][F]   (natural layout)
//   scores[b][r][d] = <rel_k[b][r], det_q[b][d]>
//   w = softmax_d(scores * 1/sqrt(F))
//   rel_add[b][r][f] = sum_d w[b][r][d] * det_v[b][d][f]   (B consumed NN)
//   out_rel[r][b][:] = LN(rel_add + rel_in) * gamma + beta
// Shapes: Nd=Nr=2048, B=8, D=F=512
// ---------------------------------------------------------------------------

#define ND 2048
#define NR 2048
#define NB 8
#define DM 512
#define DF 512

// scratch (no cudaMalloc allowed)
__device__ float g_q[(size_t)NB * ND * DF];     // det_q, later reused as rel_add
__device__ float g_k[(size_t)NB * NR * DF];     // rel_k
__device__ float g_v[(size_t)NB * ND * DF];     // det_v [b][d][f]
__device__ float g_s[(size_t)NB * NR * ND];     // scores / softmax weights

__device__ __forceinline__ uint32_t f2tf32(float f) {
    uint32_t u;
    asm("cvt.rna.tf32.f32 %0, %1;" : "=r"(u) : "f"(f));
    return u;
}

// ---------------------------------------------------------------------------
// tf32 mma.sync GEMM.
//   BNN=false (NT): C[m,n] = sum_k A[m*rsA+k] * B[n*rsB+k]
//   BNN=true  (NN): C[m,n] = sum_k A[m*rsA+k] * B[k*rsB+n]
// CTA tile 128x128, BK=16, 256 threads (8 warps, 2x4), warp tile 64x32.
// mma.m16n8k8: per warp 4 m-tiles x 4 n-tiles x 2 k-steps per slab.
// Smem layouts padded for conflict-free scalar fragment LDS:
//   As[m][k]  stride 20  -> bank(a-frag) = 20g + c   (all 32 distinct)
//   Bs NT [n][k] stride 20 -> same
//   Bs NN [k][n] stride 136 -> bank = 8c + g          (all 32 distinct)
// ---------------------------------------------------------------------------
template <bool BNN>
__global__ __launch_bounds__(256, 2) void mma_gemm(
    const float* __restrict__ A, const float* __restrict__ B, float* __restrict__ C,
    const float* __restrict__ bias, int K,
    long rsA, long bsA, long rsB, long bsB, long rsC, long bsC)
{
    __shared__ uint32_t As[2][2560];   // 128 * 20
    __shared__ uint32_t Bs[2][2560];   // max(128*20, 16*136)

    const int tid = threadIdx.x;
    const int wid = tid >> 5;
    const int lane = tid & 31;
    const int g = lane >> 2;           // 0..7
    const int c = lane & 3;            // 0..3
    const int wm = (wid >> 2) * 64;    // warp m offset
    const int wn = (wid & 3) * 32;     // warp n offset

    const long rowBase = (long)blockIdx.x * 128;
    const long colBase = (long)blockIdx.y * 128;
    A += (long)blockIdx.z * bsA;
    B += (long)blockIdx.z * bsB;
    C += (long)blockIdx.z * bsC;

    // gmem->reg load mapping (2 float4 per thread per operand per slab)
    const int arow = tid >> 2;             // 0..63 (+64 for i=1)
    const int ac4 = (tid & 3) * 4;         // k quad within 16
    const int bk = tid >> 5;               // NN: k row 0..7 (+8 for i=1)
    const int bc = (tid & 31) * 4;         // NN: n quad

    float4 ra[2], rb[2];

    float acc[4][4][4];
    #pragma unroll
    for (int mt = 0; mt < 4; mt++)
        #pragma unroll
        for (int nt = 0; nt < 4; nt++)
            #pragma unroll
            for (int r = 0; r < 4; r++) acc[mt][nt][r] = 0.f;

    const int NS = K / 16;

    // ---- prologue: load slab 0
    {
        const long k0 = 0;
        #pragma unroll
        for (int i = 0; i < 2; i++) {
            ra[i] = *reinterpret_cast<const float4*>(&A[(rowBase + arow + i * 64) * rsA + k0 + ac4]);
            if (BNN)
                rb[i] = *reinterpret_cast<const float4*>(&B[(k0 + bk + i * 8) * rsB + colBase + bc]);
            else
                rb[i] = *reinterpret_cast<const float4*>(&B[(colBase + arow + i * 64) * rsB + k0 + ac4]);
        }
        #pragma unroll
        for (int i = 0; i < 2; i++) {
            uint4 va = make_uint4(f2tf32(ra[i].x), f2tf32(ra[i].y), f2tf32(ra[i].z), f2tf32(ra[i].w));
            *reinterpret_cast<uint4*>(&As[0][(arow + i * 64) * 20 + ac4]) = va;
            uint4 vb = make_uint4(f2tf32(rb[i].x), f2tf32(rb[i].y), f2tf32(rb[i].z), f2tf32(rb[i].w));
            if (BNN)
                *reinterpret_cast<uint4*>(&Bs[0][(bk + i * 8) * 136 + bc]) = vb;
            else
                *reinterpret_cast<uint4*>(&Bs[0][(arow + i * 64) * 20 + ac4]) = vb;
        }
    }
    __syncthreads();

    for (int s = 0; s < NS; s++) {
        const int buf = s & 1;
        const bool more = (s + 1 < NS);

        if (more) {
            const long k0 = (long)(s + 1) * 16;
            #pragma unroll
            for (int i = 0; i < 2; i++) {
                ra[i] = *reinterpret_cast<const float4*>(&A[(rowBase + arow + i * 64) * rsA + k0 + ac4]);
                if (BNN)
                    rb[i] = *reinterpret_cast<const float4*>(&B[(k0 + bk + i * 8) * rsB + colBase + bc]);
                else
                    rb[i] = *reinterpret_cast<const float4*>(&B[(colBase + arow + i * 64) * rsB + k0 + ac4]);
            }
        }

        // ---- compute slab s
        #pragma unroll
        for (int kk = 0; kk < 2; kk++) {
            uint32_t a[4][4];
            #pragma unroll
            for (int mt = 0; mt < 4; mt++) {
                const int r0 = wm + mt * 16 + g;
                a[mt][0] = As[buf][(r0    ) * 20 + kk * 8 + c];
                a[mt][1] = As[buf][(r0 + 8) * 20 + kk * 8 + c];
                a[mt][2] = As[buf][(r0    ) * 20 + kk * 8 + c + 4];
                a[mt][3] = As[buf][(r0 + 8) * 20 + kk * 8 + c + 4];
            }
            uint32_t b[4][2];
            #pragma unroll
            for (int nt = 0; nt < 4; nt++) {
                const int n0 = wn + nt * 8 + g;
                if (BNN) {
                    b[nt][0] = Bs[buf][(kk * 8 + c    ) * 136 + n0];
                    b[nt][1] = Bs[buf][(kk * 8 + c + 4) * 136 + n0];
                } else {
                    b[nt][0] = Bs[buf][n0 * 20 + kk * 8 + c];
                    b[nt][1] = Bs[buf][n0 * 20 + kk * 8 + c + 4];
                }
            }
            #pragma unroll
            for (int mt = 0; mt < 4; mt++)
                #pragma unroll
                for (int nt = 0; nt < 4; nt++)
                    asm volatile(
                        "mma.sync.aligned.m16n8k8.row.col.f32.tf32.tf32.f32 "
                        "{%0,%1,%2,%3}, {%4,%5,%6,%7}, {%8,%9}, {%0,%1,%2,%3};"
                        : "+f"(acc[mt][nt][0]), "+f"(acc[mt][nt][1]),
                          "+f"(acc[mt][nt][2]), "+f"(acc[mt][nt][3])
                        : "r"(a[mt][0]), "r"(a[mt][1]), "r"(a[mt][2]), "r"(a[mt][3]),
                          "r"(b[nt][0]), "r"(b[nt][1]));
        }

        if (more) {
            const int nb = buf ^ 1;
            #pragma unroll
            for (int i = 0; i < 2; i++) {
                uint4 va = make_uint4(f2tf32(ra[i].x), f2tf32(ra[i].y), f2tf32(ra[i].z), f2tf32(ra[i].w));
                *reinterpret_cast<uint4*>(&As[nb][(arow + i * 64) * 20 + ac4]) = va;
                uint4 vb = make_uint4(f2tf32(rb[i].x), f2tf32(rb[i].y), f2tf32(rb[i].z), f2tf32(rb[i].w));
                if (BNN)
                    *reinterpret_cast<uint4*>(&Bs[nb][(bk + i * 8) * 136 + bc]) = vb;
                else
                    *reinterpret_cast<uint4*>(&Bs[nb][(arow + i * 64) * 20 + ac4]) = vb;
            }
        }
        __syncthreads();
    }

    // ---- epilogue: direct row-major stores (float2 pairs), optional bias
    #pragma unroll
    for (int mt = 0; mt < 4; mt++) {
        const long row = rowBase + wm + mt * 16 + g;
        #pragma unroll
        for (int nt = 0; nt < 4; nt++) {
            const long col = colBase + wn + nt * 8 + 2 * c;
            float bx = 0.f, by = 0.f;
            if (bias) { bx = bias[col]; by = bias[col + 1]; }
            float2 v0 = make_float2(acc[mt][nt][0] + bx, acc[mt][nt][1] + by);
            float2 v1 = make_float2(acc[mt][nt][2] + bx, acc[mt][nt][3] + by);
            *reinterpret_cast<float2*>(&C[row * rsC + col]) = v0;
            *reinterpret_cast<float2*>(&C[(row + 8) * rsC + col]) = v1;
        }
    }
}

// ---------------------------------------------------------------------------
// In-place scaled softmax over rows: softmax(x * scale)
// ---------------------------------------------------------------------------
__global__ __launch_bounds__(256) void softmax_rows(float* __restrict__ S, int cols, float scale)
{
    float* p = S + (long)blockIdx.x * cols;
    const int tid = threadIdx.x;
    __shared__ float red[256];

    float m = -INFINITY;
    for (int c = tid * 4; c < cols; c += 1024) {
        float4 v = *reinterpret_cast<const float4*>(&p[c]);
        m = fmaxf(m, fmaxf(fmaxf(v.x, v.y), fmaxf(v.z, v.w)));
    }
    red[tid] = m; __syncthreads();
    for (int s = 128; s > 0; s >>= 1) {
        if (tid < s) red[tid] = fmaxf(red[tid], red[tid + s]);
        __syncthreads();
    }
    m = red[0];
    __syncthreads();

    float sum = 0.f;
    for (int c = tid * 4; c < cols; c += 1024) {
        float4 v = *reinterpret_cast<const float4*>(&p[c]);
        v.x = __expf((v.x - m) * scale); v.y = __expf((v.y - m) * scale);
        v.z = __expf((v.z - m) * scale); v.w = __expf((v.w - m) * scale);
        *reinterpret_cast<float4*>(&p[c]) = v;
        sum += v.x + v.y + v.z + v.w;
    }
    red[tid] = sum; __syncthreads();
    for (int s = 128; s > 0; s >>= 1) {
        if (tid < s) red[tid] += red[tid + s];
        __syncthreads();
    }
    const float inv = 1.f / red[0];

    for (int c = tid * 4; c < cols; c += 1024) {
        float4 v = *reinterpret_cast<const float4*>(&p[c]);
        v.x *= inv; v.y *= inv; v.z *= inv; v.w *= inv;
        *reinterpret_cast<float4*>(&p[c]) = v;
    }
}

// ---------------------------------------------------------------------------
// out[r][b][:] = LN(add[b][r][:] + rel_in[r][b][:]) * gamma + beta
// ---------------------------------------------------------------------------
__global__ __launch_bounds__(128) void residual_ln(
    const float* __restrict__ add, const float* __restrict__ rel_in,
    const float* __restrict__ gamma, const float* __restrict__ beta,
    float* __restrict__ out)
{
    const long idx = blockIdx.x;          // b*NR + r
    const long b = idx >> 11;
    const long r = idx & 2047;
    const int tid = threadIdx.x;
    const int f = tid * 4;

    const float4 a4 = *reinterpret_cast<const float4*>(&add[idx * DM + f]);
    const float4 r4 = *reinterpret_cast<const float4*>(&rel_in[(r * NB + b) * DM + f]);
    float x0 = a4.x + r4.x, x1 = a4.y + r4.y, x2 = a4.z + r4.z, x3 = a4.w + r4.w;

    float sum = x0 + x1 + x2 + x3;
    float ssq = x0 * x0 + x1 * x1 + x2 * x2 + x3 * x3;
    #pragma unroll
    for (int o = 16; o > 0; o >>= 1) {
        sum += __shfl_xor_sync(0xFFFFFFFFu, sum, o);
        ssq += __shfl_xor_sync(0xFFFFFFFFu, ssq, o);
    }
    __shared__ float s1[4], s2[4];
    const int w = tid >> 5;
    if ((tid & 31) == 0) { s1[w] = sum; s2[w] = ssq; }
    __syncthreads();
    sum = s1[0] + s1[1] + s1[2] + s1[3];
    ssq = s2[0] + s2[1] + s2[2] + s2[3];

    const float mean = sum * (1.f / DM);
    const float var = ssq * (1.f / DM) - mean * mean;
    const float rstd = rsqrtf(var + 1e-5f);

    const float4 g4 = *reinterpret_cast<const float4*>(&gamma[f]);
    const float4 be4 = *reinterpret_cast<const float4*>(&beta[f]);
    float4 o4;
    o4.x = (x0 - mean) * rstd * g4.x + be4.x;
    o4.y = (x1 - mean) * rstd * g4.y + be4.y;
    o4.z = (x2 - mean) * rstd * g4.z + be4.z;
    o4.w = (x3 - mean) * rstd * g4.w + be4.w;
    *reinterpret_cast<float4*>(&out[(r * NB + b) * DM + f]) = o4;
}

// ---------------------------------------------------------------------------
extern "C" void kernel_launch(void* const* d_in, const int* in_sizes, int n_in,
                              void* d_out, int out_size)
{
    const float* det_in = (const float*)d_in[0];
    const float* rel_in = (const float*)d_in[1];
    const float* W_det  = (const float*)d_in[2];
    const float* b_det  = (const float*)d_in[3];
    const float* W_rel  = (const float*)d_in[4];
    const float* b_rel  = (const float*)d_in[5];
    const float* W_val  = (const float*)d_in[6];
    const float* b_val  = (const float*)d_in[7];
    const float* gamma  = (const float*)d_in[8];
    const float* beta   = (const float*)d_in[9];
    float* out = (float*)d_out;

    float *q, *k, *v, *s;
    cudaGetSymbolAddress((void**)&q, g_q);
    cudaGetSymbolAddress((void**)&k, g_k);
    cudaGetSymbolAddress((void**)&v, g_v);
    cudaGetSymbolAddress((void**)&s, g_s);

    // Pass-through: out[0 : Nd*B*D] = det_in
    cudaMemcpyAsync(out, det_in, (size_t)ND * NB * DM * sizeof(float),
                    cudaMemcpyDeviceToDevice);

    dim3 blk(256);

    // --- projections (NT): A rows = token (stride NB*DM), batch offset DM
    dim3 gp(ND / 128, DF / 128, NB);
    mma_gemm<false><<<gp, blk>>>(det_in, W_det, q, b_det, DM,
                                 (long)NB * DM, DM, DM, 0, DF, (long)ND * DF);
    mma_gemm<false><<<gp, blk>>>(rel_in, W_rel, k, b_rel, DM,
                                 (long)NB * DM, DM, DM, 0, DF, (long)NR * DF);
    mma_gemm<false><<<gp, blk>>>(det_in, W_val, v, b_val, DM,
                                 (long)NB * DM, DM, DM, 0, DF, (long)ND * DF);

    // --- scores[b][r][d] = <rel_k[b][r], det_q[b][d]>  (NT; scale in softmax)
    dim3 gs(NR / 128, ND / 128, NB);
    mma_gemm<false><<<gs, blk>>>(k, q, s, nullptr, DF,
                                 DF, (long)NR * DF, DF, (long)ND * DF,
                                 ND, (long)NR * ND);

    // --- softmax over det axis, scaled by 1/sqrt(F)
    softmax_rows<<<NB * NR, 256>>>(s, ND, 1.f / sqrtf((float)DF));

    // --- rel_add[b][r][f] = sum_d w[b][r][d] * v[b][d][f]   (NN; reuse q)
    dim3 ga(NR / 128, DF / 128, NB);
    mma_gemm<true><<<ga, blk>>>(s, v, q, nullptr, ND,
                                ND, (long)NR * ND, DF, (long)ND * DF,
                                DF, (long)NR * DF);

    // --- residual + LayerNorm -> out[Nd*B*D + ...]
    residual_ln<<<NB * NR, 128>>>(q, rel_in, gamma, beta,
                                  out + (size_t)ND * NB * DM);
}

// round 4
// speedup vs baseline: 2.8601x; 1.0352x over previous
#include <cuda_runtime.h>
#include <cstdint>
#include <math.h>

// ---------------------------------------------------------------------------
// InteractionLayer via tf32 mma.sync + cp.async (arch-portable PTX, sm_103).
//   det_q = det_in @ W_det^T + b_det        [B][Nd][F]
//   rel_k = rel_in @ W_rel^T + b_rel        [B][Nr][F]
//   det_v = det_in @ W_val^T + b_val        [B][Nd][F]
//   e[b][r][d] = exp((<rel_k,det_q> - rowmax) / sqrt(F));  inv[b][r]=1/rowsum
//   rel_add[b][r][f] = (sum_d e * det_v) * inv[b][r]     (scale in AV epilogue)
//   out_rel[r][b][:] = LN(rel_add + rel_in) * gamma + beta
// GEMM: CTA tile 128x256, 8 warps (2x4), warp tile 64x64, BK=16,
// double-buffered cp.async, raw fp32 -> mma.tf32 (HW truncation).
// ---------------------------------------------------------------------------

#define ND 2048
#define NR 2048
#define NB 8
#define DM 512
#define DF 512

// scratch (no cudaMalloc allowed)
__device__ float g_q[(size_t)NB * ND * DF];     // det_q, later reused as rel_add
__device__ float g_k[(size_t)NB * NR * DF];     // rel_k
__device__ float g_v[(size_t)NB * ND * DF];     // det_v [b][d][f]
__device__ float g_s[(size_t)NB * NR * ND];     // scores / exp weights
__device__ float g_inv[(size_t)NB * NR];        // 1/rowsum

__device__ __forceinline__ uint32_t smem_u32(const void* p) {
    uint32_t a;
    asm("{ .reg .u64 t; cvta.to.shared.u64 t, %1; cvt.u32.u64 %0, t; }" : "=r"(a) : "l"(p));
    return a;
}
__device__ __forceinline__ void cp16(uint32_t dst, const void* src) {
    asm volatile("cp.async.ca.shared.global [%0], [%1], 16;" :: "r"(dst), "l"(src) : "memory");
}
#define CP_COMMIT() asm volatile("cp.async.commit_group;" ::: "memory")
#define CP_WAIT0()  asm volatile("cp.async.wait_group 0;" ::: "memory")

// smem word layout (dynamic):
//   As[buf] : 128 rows * 20 stride   -> base  buf*2560          (2 bufs: 5120)
//   Bs[buf] : NT 256*20 / NN 16*264  -> base  5120 + buf*5120   (2 bufs: 10240)
#define AS_STRIDE 20
#define BS_NT_STRIDE 20
#define BS_NN_STRIDE 264
#define AS_WORDS 2560
#define BS_WORDS 5120
#define SMEM_WORDS (2 * AS_WORDS + 2 * BS_WORDS)
#define SMEM_BYTES (SMEM_WORDS * 4)

// ---------------------------------------------------------------------------
// BNN=false (NT): C[m,n] = sum_k A[m*rsA+k] * B[n*rsB+k]
// BNN=true  (NN): C[m,n] = sum_k A[m*rsA+k] * B[k*rsB+n]
// Optional bias[n]; optional rowScale (per-row multiplier, indexed bz*ssS+row).
// ---------------------------------------------------------------------------
template <bool BNN>
__global__ __launch_bounds__(256, 1) void mma_gemm(
    const float* __restrict__ A, const float* __restrict__ B, float* __restrict__ C,
    const float* __restrict__ bias, const float* __restrict__ rowScale, long ssS,
    int K, long rsA, long bsA, long rsB, long bsB, long rsC, long bsC)
{
    extern __shared__ uint32_t dyn[];
    const uint32_t sb = smem_u32(dyn);

    const int tid = threadIdx.x;
    const int wid = tid >> 5;
    const int lane = tid & 31;
    const int g = lane >> 2;            // 0..7
    const int c = lane & 3;             // 0..3
    const int wm = (wid >> 2) * 64;     // warp m offset (0/64)
    const int wn = (wid & 3) * 64;      // warp n offset (0..192)

    const long rowBase = (long)blockIdx.x * 128;
    const long colBase = (long)blockIdx.y * 256;
    A += (long)blockIdx.z * bsA;
    B += (long)blockIdx.z * bsB;
    C += (long)blockIdx.z * bsC;

    // cp.async mappings
    const int arow = tid >> 2;          // 0..63 (+64)
    const int ac4 = (tid & 3) * 4;      // k quad (words)
    const int nnk = tid >> 4;           // 0..15 (NN k row)
    const int nncol = (tid & 15) * 16;  // NN col base (4 float4)

    float acc[4][8][4];
    #pragma unroll
    for (int mt = 0; mt < 4; mt++)
        #pragma unroll
        for (int nt = 0; nt < 8; nt++)
            #pragma unroll
            for (int r = 0; r < 4; r++) acc[mt][nt][r] = 0.f;

    const int NS = K / 16;

    auto issue = [&](int s, int buf) {
        const long k0 = (long)s * 16;
        const uint32_t asb = sb + (buf * AS_WORDS) * 4;
        const uint32_t bsb = sb + (2 * AS_WORDS + buf * BS_WORDS) * 4;
        #pragma unroll
        for (int i = 0; i < 2; i++) {
            const int r = arow + i * 64;
            cp16(asb + (r * AS_STRIDE + ac4) * 4, &A[(rowBase + r) * rsA + k0 + ac4]);
        }
        if (BNN) {
            #pragma unroll
            for (int i = 0; i < 4; i++) {
                const int col = nncol + i * 4;
                cp16(bsb + (nnk * BS_NN_STRIDE + col) * 4,
                     &B[(k0 + nnk) * rsB + colBase + col]);
            }
        } else {
            #pragma unroll
            for (int i = 0; i < 4; i++) {
                const int r = arow + i * 64;
                cp16(bsb + (r * BS_NT_STRIDE + ac4) * 4,
                     &B[(colBase + r) * rsB + k0 + ac4]);
            }
        }
        CP_COMMIT();
    };

    issue(0, 0);

    for (int s = 0; s < NS; s++) {
        const int buf = s & 1;
        CP_WAIT0();
        __syncthreads();
        if (s + 1 < NS) issue(s + 1, buf ^ 1);

        const uint32_t* As = dyn + buf * AS_WORDS;
        const uint32_t* Bsb = dyn + 2 * AS_WORDS + buf * BS_WORDS;

        #pragma unroll
        for (int kk = 0; kk < 2; kk++) {
            uint32_t a[4][4];
            #pragma unroll
            for (int mt = 0; mt < 4; mt++) {
                const int r0 = wm + mt * 16 + g;
                a[mt][0] = As[(r0    ) * AS_STRIDE + kk * 8 + c];
                a[mt][1] = As[(r0 + 8) * AS_STRIDE + kk * 8 + c];
                a[mt][2] = As[(r0    ) * AS_STRIDE + kk * 8 + c + 4];
                a[mt][3] = As[(r0 + 8) * AS_STRIDE + kk * 8 + c + 4];
            }
            uint32_t b[8][2];
            #pragma unroll
            for (int nt = 0; nt < 8; nt++) {
                const int n0 = wn + nt * 8 + g;
                if (BNN) {
                    b[nt][0] = Bsb[(kk * 8 + c    ) * BS_NN_STRIDE + n0];
                    b[nt][1] = Bsb[(kk * 8 + c + 4) * BS_NN_STRIDE + n0];
                } else {
                    b[nt][0] = Bsb[n0 * BS_NT_STRIDE + kk * 8 + c];
                    b[nt][1] = Bsb[n0 * BS_NT_STRIDE + kk * 8 + c + 4];
                }
            }
            #pragma unroll
            for (int mt = 0; mt < 4; mt++)
                #pragma unroll
                for (int nt = 0; nt < 8; nt++)
                    asm volatile(
                        "mma.sync.aligned.m16n8k8.row.col.f32.tf32.tf32.f32 "
                        "{%0,%1,%2,%3}, {%4,%5,%6,%7}, {%8,%9}, {%0,%1,%2,%3};"
                        : "+f"(acc[mt][nt][0]), "+f"(acc[mt][nt][1]),
                          "+f"(acc[mt][nt][2]), "+f"(acc[mt][nt][3])
                        : "r"(a[mt][0]), "r"(a[mt][1]), "r"(a[mt][2]), "r"(a[mt][3]),
                          "r"(b[nt][0]), "r"(b[nt][1]));
        }
        __syncthreads();
    }

    // ---- epilogue: direct row-major stores, optional bias + per-row scale
    #pragma unroll
    for (int mt = 0; mt < 4; mt++) {
        const long row0 = rowBase + wm + mt * 16 + g;
        float sc0 = 1.f, sc1 = 1.f;
        if (rowScale) {
            sc0 = rowScale[(long)blockIdx.z * ssS + row0];
            sc1 = rowScale[(long)blockIdx.z * ssS + row0 + 8];
        }
        #pragma unroll
        for (int nt = 0; nt < 8; nt++) {
            const long col = colBase + wn + nt * 8 + 2 * c;
            float bx = 0.f, by = 0.f;
            if (bias) { bx = bias[col]; by = bias[col + 1]; }
            float2 v0 = make_float2(acc[mt][nt][0] * sc0 + bx, acc[mt][nt][1] * sc0 + by);
            float2 v1 = make_float2(acc[mt][nt][2] * sc1 + bx, acc[mt][nt][3] * sc1 + by);
            *reinterpret_cast<float2*>(&C[row0 * rsC + col]) = v0;
            *reinterpret_cast<float2*>(&C[(row0 + 8) * rsC + col]) = v1;
        }
    }
}

// ---------------------------------------------------------------------------
// Softmax pass 1+2: p[:] = exp((p[:] - max) * scale); inv[row] = 1/sum.
// Normalization deferred to AV epilogue.
// ---------------------------------------------------------------------------
__global__ __launch_bounds__(256) void softmax_exp(float* __restrict__ S, int cols,
                                                   float scale, float* __restrict__ inv)
{
    float* p = S + (long)blockIdx.x * cols;
    const int tid = threadIdx.x;
    __shared__ float red[256];

    float m = -INFINITY;
    for (int c = tid * 4; c < cols; c += 1024) {
        float4 v = *reinterpret_cast<const float4*>(&p[c]);
        m = fmaxf(m, fmaxf(fmaxf(v.x, v.y), fmaxf(v.z, v.w)));
    }
    red[tid] = m; __syncthreads();
    for (int s = 128; s > 0; s >>= 1) {
        if (tid < s) red[tid] = fmaxf(red[tid], red[tid + s]);
        __syncthreads();
    }
    m = red[0];
    __syncthreads();

    float sum = 0.f;
    for (int c = tid * 4; c < cols; c += 1024) {
        float4 v = *reinterpret_cast<const float4*>(&p[c]);
        v.x = __expf((v.x - m) * scale); v.y = __expf((v.y - m) * scale);
        v.z = __expf((v.z - m) * scale); v.w = __expf((v.w - m) * scale);
        *reinterpret_cast<float4*>(&p[c]) = v;
        sum += v.x + v.y + v.z + v.w;
    }
    red[tid] = sum; __syncthreads();
    for (int s = 128; s > 0; s >>= 1) {
        if (tid < s) red[tid] += red[tid + s];
        __syncthreads();
    }
    if (tid == 0) inv[blockIdx.x] = 1.f / red[0];
}

// ---------------------------------------------------------------------------
// out[r][b][:] = LN(add[b][r][:] + rel_in[r][b][:]) * gamma + beta
// ---------------------------------------------------------------------------
__global__ __launch_bounds__(128) void residual_ln(
    const float* __restrict__ add, const float* __restrict__ rel_in,
    const float* __restrict__ gamma, const float* __restrict__ beta,
    float* __restrict__ out)
{
    const long idx = blockIdx.x;          // b*NR + r
    const long b = idx >> 11;
    const long r = idx & 2047;
    const int tid = threadIdx.x;
    const int f = tid * 4;

    const float4 a4 = *reinterpret_cast<const float4*>(&add[idx * DM + f]);
    const float4 r4 = *reinterpret_cast<const float4*>(&rel_in[(r * NB + b) * DM + f]);
    float x0 = a4.x + r4.x, x1 = a4.y + r4.y, x2 = a4.z + r4.z, x3 = a4.w + r4.w;

    float sum = x0 + x1 + x2 + x3;
    float ssq = x0 * x0 + x1 * x1 + x2 * x2 + x3 * x3;
    #pragma unroll
    for (int o = 16; o > 0; o >>= 1) {
        sum += __shfl_xor_sync(0xFFFFFFFFu, sum, o);
        ssq += __shfl_xor_sync(0xFFFFFFFFu, ssq, o);
    }
    __shared__ float s1[4], s2[4];
    const int w = tid >> 5;
    if ((tid & 31) == 0) { s1[w] = sum; s2[w] = ssq; }
    __syncthreads();
    sum = s1[0] + s1[1] + s1[2] + s1[3];
    ssq = s2[0] + s2[1] + s2[2] + s2[3];

    const float mean = sum * (1.f / DM);
    const float var = ssq * (1.f / DM) - mean * mean;
    const float rstd = rsqrtf(var + 1e-5f);

    const float4 g4 = *reinterpret_cast<const float4*>(&gamma[f]);
    const float4 be4 = *reinterpret_cast<const float4*>(&beta[f]);
    float4 o4;
    o4.x = (x0 - mean) * rstd * g4.x + be4.x;
    o4.y = (x1 - mean) * rstd * g4.y + be4.y;
    o4.z = (x2 - mean) * rstd * g4.z + be4.z;
    o4.w = (x3 - mean) * rstd * g4.w + be4.w;
    *reinterpret_cast<float4*>(&out[(r * NB + b) * DM + f]) = o4;
}

// ---------------------------------------------------------------------------
extern "C" void kernel_launch(void* const* d_in, const int* in_sizes, int n_in,
                              void* d_out, int out_size)
{
    const float* det_in = (const float*)d_in[0];
    const float* rel_in = (const float*)d_in[1];
    const float* W_det  = (const float*)d_in[2];
    const float* b_det  = (const float*)d_in[3];
    const float* W_rel  = (const float*)d_in[4];
    const float* b_rel  = (const float*)d_in[5];
    const float* W_val  = (const float*)d_in[6];
    const float* b_val  = (const float*)d_in[7];
    const float* gamma  = (const float*)d_in[8];
    const float* beta   = (const float*)d_in[9];
    float* out = (float*)d_out;

    float *q, *k, *v, *s, *inv;
    cudaGetSymbolAddress((void**)&q, g_q);
    cudaGetSymbolAddress((void**)&k, g_k);
    cudaGetSymbolAddress((void**)&v, g_v);
    cudaGetSymbolAddress((void**)&s, g_s);
    cudaGetSymbolAddress((void**)&inv, g_inv);

    static bool attrSet = false;
    if (!attrSet) {
        cudaFuncSetAttribute(mma_gemm<false>, cudaFuncAttributeMaxDynamicSharedMemorySize, SMEM_BYTES);
        cudaFuncSetAttribute(mma_gemm<true>,  cudaFuncAttributeMaxDynamicSharedMemorySize, SMEM_BYTES);
        attrSet = true;
    }

    // Pass-through: out[0 : Nd*B*D] = det_in
    cudaMemcpyAsync(out, det_in, (size_t)ND * NB * DM * sizeof(float),
                    cudaMemcpyDeviceToDevice);

    dim3 blk(256);

    // --- projections (NT): A rows = token (stride NB*DM), batch offset DM
    dim3 gp(ND / 128, DF / 256, NB);
    mma_gemm<false><<<gp, blk, SMEM_BYTES>>>(det_in, W_det, q, b_det, nullptr, 0, DM,
                                             (long)NB * DM, DM, DM, 0, DF, (long)ND * DF);
    mma_gemm<false><<<gp, blk, SMEM_BYTES>>>(rel_in, W_rel, k, b_rel, nullptr, 0, DM,
                                             (long)NB * DM, DM, DM, 0, DF, (long)NR * DF);
    mma_gemm<false><<<gp, blk, SMEM_BYTES>>>(det_in, W_val, v, b_val, nullptr, 0, DM,
                                             (long)NB * DM, DM, DM, 0, DF, (long)ND * DF);

    // --- scores[b][r][d] = <rel_k[b][r], det_q[b][d]>  (NT)
    dim3 gs(NR / 128, ND / 256, NB);
    mma_gemm<false><<<gs, blk, SMEM_BYTES>>>(k, q, s, nullptr, nullptr, 0, DF,
                                             DF, (long)NR * DF, DF, (long)ND * DF,
                                             ND, (long)NR * ND);

    // --- exp + row-sum inverse (normalization folded into AV epilogue)
    softmax_exp<<<NB * NR, 256>>>(s, ND, 1.f / sqrtf((float)DF), inv);

    // --- rel_add[b][r][f] = (sum_d e * v) * inv[b][r]   (NN; reuse q)
    dim3 ga(NR / 128, DF / 256, NB);
    mma_gemm<true><<<ga, blk, SMEM_BYTES>>>(s, v, q, nullptr, inv, NR, ND,
                                            ND, (long)NR * ND, DF, (long)ND * DF,
                                            DF, (long)NR * DF);

    // --- residual + LayerNorm -> out[Nd*B*D + ...]
    residual_ln<<<NB * NR, 128>>>(q, rel_in, gamma, beta,
                                  out + (size_t)ND * NB * DM);
}

// round 5
// speedup vs baseline: 5.1013x; 1.7836x over previous
#include <cuda_runtime.h>
#include <cuda_fp16.h>
#include <cstdint>
#include <math.h>

// ---------------------------------------------------------------------------
// InteractionLayer via fp16 mma.sync m16n8k16 + cp.async + ldmatrix
// (all arch-portable PTX; harness targets plain sm_103 — no 'a' features).
// fp16 operands (10-bit mantissa, same as tf32), fp32 accumulate.
//   det_q/rel_k/det_v = proj(in) @ W^T + b        -> fp16
//   scores = rel_k @ det_q^T                      -> fp32
//   e = exp((scores - rowmax)/sqrt(F)) -> fp16;  inv = 1/rowsum
//   rel_add = (e @ det_v) * inv                   -> fp32
//   out_rel = LN(rel_add + rel_in) * gamma + beta
// GEMM: CTA 128x256, 16 warps (2x8) of 64x32, BK=32, double-buffered cp.async.
// ---------------------------------------------------------------------------

#define ND 2048
#define NR 2048
#define NB 8
#define DM 512
#define DF 512

// scratch (no cudaMalloc allowed)
__device__ __align__(16) __half g_det16[(size_t)ND * NB * DM];
__device__ __align__(16) __half g_rel16[(size_t)NR * NB * DM];
__device__ __align__(16) __half g_wd16[(size_t)DF * DM];
__device__ __align__(16) __half g_wr16[(size_t)DF * DM];
__device__ __align__(16) __half g_wv16[(size_t)DF * DM];
__device__ __align__(16) __half g_q16[(size_t)NB * ND * DF];
__device__ __align__(16) __half g_k16[(size_t)NB * NR * DF];
__device__ __align__(16) __half g_v16[(size_t)NB * ND * DF];
__device__ __align__(16) __half g_e16[(size_t)NB * NR * ND];
__device__ __align__(16) float  g_s[(size_t)NB * NR * ND];
__device__ __align__(16) float  g_add[(size_t)NB * NR * DF];
__device__ float g_inv[(size_t)NB * NR];

__device__ __forceinline__ uint32_t smem_u32(const void* p) {
    uint32_t a;
    asm("{ .reg .u64 t; cvta.to.shared.u64 t, %1; cvt.u32.u64 %0, t; }" : "=r"(a) : "l"(p));
    return a;
}
__device__ __forceinline__ void cp16(uint32_t dst, const void* src) {
    asm volatile("cp.async.ca.shared.global [%0], [%1], 16;" :: "r"(dst), "l"(src) : "memory");
}
#define CP_COMMIT() asm volatile("cp.async.commit_group;" ::: "memory")

__device__ __forceinline__ void ldsm4(uint32_t* r, uint32_t a) {
    asm volatile("ldmatrix.sync.aligned.m8n8.x4.shared.b16 {%0,%1,%2,%3}, [%4];"
                 : "=r"(r[0]), "=r"(r[1]), "=r"(r[2]), "=r"(r[3]) : "r"(a));
}
__device__ __forceinline__ void ldsm4t(uint32_t* r, uint32_t a) {
    asm volatile("ldmatrix.sync.aligned.m8n8.x4.trans.shared.b16 {%0,%1,%2,%3}, [%4];"
                 : "=r"(r[0]), "=r"(r[1]), "=r"(r[2]), "=r"(r[3]) : "r"(a));
}

// smem halves layout (per buffer 30720 B): As 128x40 h (10240 B), Bs 20480 B
// (NT: 256x40 h; NN: 32x264 h). Two buffers: 61440 B.
#define AS_STRIDE 40
#define BNT_STRIDE 40
#define BNN_STRIDE 264
#define BUF_BYTES 30720
#define SMEM_BYTES (2 * BUF_BYTES)

// ---------------------------------------------------------------------------
// BNN=false (NT): C[m,n] = sum_k A[m*rsA+k] * B[n*rsB+k]
// BNN=true  (NN): C[m,n] = sum_k A[m*rsA+k] * B[k*rsB+n]
// Strides in elements (halves for A/B, OutT for C).
// ---------------------------------------------------------------------------
template <bool BNN, typename OutT>
__global__ __launch_bounds__(512, 1) void hgemm(
    const __half* __restrict__ A, const __half* __restrict__ B, OutT* __restrict__ C,
    const float* __restrict__ bias, const float* __restrict__ rowScale, long ssS,
    int K, long rsA, long bsA, long rsB, long bsB, long rsC, long bsC)
{
    extern __shared__ __align__(16) char dyn[];
    const uint32_t sb = smem_u32(dyn);

    const int tid = threadIdx.x;
    const int wid = tid >> 5;
    const int lane = tid & 31;
    const int g = lane >> 2;
    const int c = lane & 3;
    const int t8 = lane >> 3;           // ldmatrix tile index
    const int lr = lane & 7;            // ldmatrix row within tile
    const int wm = (wid >> 3) * 64;     // warp m offset: 0 / 64
    const int wn = (wid & 7) * 32;      // warp n offset: 0..224

    const long rowBase = (long)blockIdx.x * 128;
    const long colBase = (long)blockIdx.y * 256;
    A += (long)blockIdx.z * bsA;
    B += (long)blockIdx.z * bsB;
    C += (long)blockIdx.z * bsC;

    float acc[4][4][4];
    #pragma unroll
    for (int mt = 0; mt < 4; mt++)
        #pragma unroll
        for (int nt = 0; nt < 4; nt++)
            #pragma unroll
            for (int r = 0; r < 4; r++) acc[mt][nt][r] = 0.f;

    const int NS = K / 32;

    auto issue = [&](int s) {
        const int buf = s & 1;
        const long k0 = (long)s * 32;
        const uint32_t ab = sb + buf * BUF_BYTES;
        const uint32_t bb = ab + 10240;
        {   // A: 128 rows x 4 chunks (8 halves each) = 512 cp16
            const int row = tid >> 2, ch = tid & 3;
            cp16(ab + (row * AS_STRIDE + ch * 8) * 2,
                 &A[(rowBase + row) * rsA + k0 + ch * 8]);
        }
        if (BNN) {                      // B: 32 k-rows x 32 chunks = 1024 cp16
            #pragma unroll
            for (int i = 0; i < 2; i++) {
                const int idx = i * 512 + tid;
                const int kr = idx >> 5, ch = idx & 31;
                cp16(bb + (kr * BNN_STRIDE + ch * 8) * 2,
                     &B[(k0 + kr) * rsB + colBase + ch * 8]);
            }
        } else {                        // B: 256 rows x 4 chunks = 1024 cp16
            #pragma unroll
            for (int i = 0; i < 2; i++) {
                const int idx = i * 512 + tid;
                const int row = idx >> 2, ch = idx & 3;
                cp16(bb + (row * BNT_STRIDE + ch * 8) * 2,
                     &B[(colBase + row) * rsB + k0 + ch * 8]);
            }
        }
        CP_COMMIT();
    };

    issue(0);
    if (NS > 1) issue(1);

    for (int s = 0; s < NS; s++) {
        if (s + 1 < NS)
            asm volatile("cp.async.wait_group 1;" ::: "memory");
        else
            asm volatile("cp.async.wait_group 0;" ::: "memory");
        __syncthreads();

        const uint32_t ab = sb + (s & 1) * BUF_BYTES;
        const uint32_t bb = ab + 10240;

        #pragma unroll
        for (int kk = 0; kk < 2; kk++) {
            const int k0h = kk * 16;
            uint32_t a[4][4];
            #pragma unroll
            for (int mt = 0; mt < 4; mt++)
                ldsm4(a[mt], ab + ((wm + mt * 16 + (t8 & 1) * 8 + lr) * AS_STRIDE
                                   + k0h + (t8 >> 1) * 8) * 2);
            uint32_t b[2][4];
            #pragma unroll
            for (int np = 0; np < 2; np++) {
                if (BNN)
                    ldsm4t(b[np], bb + ((k0h + (t8 & 1) * 8 + lr) * BNN_STRIDE
                                        + wn + np * 16 + (t8 >> 1) * 8) * 2);
                else
                    ldsm4(b[np], bb + ((wn + np * 16 + (t8 >> 1) * 8 + lr) * BNT_STRIDE
                                       + k0h + (t8 & 1) * 8) * 2);
            }
            #pragma unroll
            for (int mt = 0; mt < 4; mt++)
                #pragma unroll
                for (int nt = 0; nt < 4; nt++)
                    asm volatile(
                        "mma.sync.aligned.m16n8k16.row.col.f32.f16.f16.f32 "
                        "{%0,%1,%2,%3}, {%4,%5,%6,%7}, {%8,%9}, {%0,%1,%2,%3};"
                        : "+f"(acc[mt][nt][0]), "+f"(acc[mt][nt][1]),
                          "+f"(acc[mt][nt][2]), "+f"(acc[mt][nt][3])
                        : "r"(a[mt][0]), "r"(a[mt][1]), "r"(a[mt][2]), "r"(a[mt][3]),
                          "r"(b[nt >> 1][(nt & 1) * 2]), "r"(b[nt >> 1][(nt & 1) * 2 + 1]));
        }
        __syncthreads();
        if (s + 2 < NS) issue(s + 2);
    }

    // ---- epilogue
    #pragma unroll
    for (int mt = 0; mt < 4; mt++) {
        const long row0 = rowBase + wm + mt * 16 + g;
        float sc0 = 1.f, sc1 = 1.f;
        if (rowScale) {
            sc0 = rowScale[(long)blockIdx.z * ssS + row0];
            sc1 = rowScale[(long)blockIdx.z * ssS + row0 + 8];
        }
        #pragma unroll
        for (int nt = 0; nt < 4; nt++) {
            const long col = colBase + wn + nt * 8 + 2 * c;
            float bx = 0.f, by = 0.f;
            if (bias) { bx = bias[col]; by = bias[col + 1]; }
            float x0 = acc[mt][nt][0] * sc0 + bx, x1 = acc[mt][nt][1] * sc0 + by;
            float x2 = acc[mt][nt][2] * sc1 + bx, x3 = acc[mt][nt][3] * sc1 + by;
            if (sizeof(OutT) == 2) {
                __half2* p0 = reinterpret_cast<__half2*>(C + row0 * rsC + col);
                __half2* p1 = reinterpret_cast<__half2*>(C + (row0 + 8) * rsC + col);
                *p0 = __floats2half2_rn(x0, x1);
                *p1 = __floats2half2_rn(x2, x3);
            } else {
                *reinterpret_cast<float2*>((float*)C + row0 * rsC + col) = make_float2(x0, x1);
                *reinterpret_cast<float2*>((float*)C + (row0 + 8) * rsC + col) = make_float2(x2, x3);
            }
        }
    }
}

// ---------------------------------------------------------------------------
// fp32 -> fp16 conversion (n multiple of 4)
// ---------------------------------------------------------------------------
__global__ __launch_bounds__(256) void cvt16(const float* __restrict__ src,
                                             __half* __restrict__ dst, long n)
{
    long i = ((long)blockIdx.x * blockDim.x + threadIdx.x) * 4;
    const long stride = (long)gridDim.x * blockDim.x * 4;
    for (; i < n; i += stride) {
        float4 v = *reinterpret_cast<const float4*>(src + i);
        __half2* p = reinterpret_cast<__half2*>(dst + i);
        p[0] = __floats2half2_rn(v.x, v.y);
        p[1] = __floats2half2_rn(v.z, v.w);
    }
}

// ---------------------------------------------------------------------------
// e[:] = exp((s - rowmax)*scale) as fp16; inv[row] = 1/rowsum (fp32 math).
// ---------------------------------------------------------------------------
__global__ __launch_bounds__(256) void softmax_exp(
    const float* __restrict__ S, __half* __restrict__ E, int cols,
    float scale, float* __restrict__ inv)
{
    const float* p = S + (long)blockIdx.x * cols;
    __half* q = E + (long)blockIdx.x * cols;
    const int tid = threadIdx.x;
    __shared__ float red[256];

    float m = -INFINITY;
    for (int c = tid * 4; c < cols; c += 1024) {
        float4 v = *reinterpret_cast<const float4*>(&p[c]);
        m = fmaxf(m, fmaxf(fmaxf(v.x, v.y), fmaxf(v.z, v.w)));
    }
    red[tid] = m; __syncthreads();
    for (int s = 128; s > 0; s >>= 1) {
        if (tid < s) red[tid] = fmaxf(red[tid], red[tid + s]);
        __syncthreads();
    }
    m = red[0];
    __syncthreads();

    float sum = 0.f;
    for (int c = tid * 4; c < cols; c += 1024) {
        float4 v = *reinterpret_cast<const float4*>(&p[c]);
        float e0 = __expf((v.x - m) * scale), e1 = __expf((v.y - m) * scale);
        float e2 = __expf((v.z - m) * scale), e3 = __expf((v.w - m) * scale);
        __half2* h = reinterpret_cast<__half2*>(&q[c]);
        h[0] = __floats2half2_rn(e0, e1);
        h[1] = __floats2half2_rn(e2, e3);
        sum += e0 + e1 + e2 + e3;
    }
    red[tid] = sum; __syncthreads();
    for (int s = 128; s > 0; s >>= 1) {
        if (tid < s) red[tid] += red[tid + s];
        __syncthreads();
    }
    if (tid == 0) inv[blockIdx.x] = 1.f / red[0];
}

// ---------------------------------------------------------------------------
// out[r][b][:] = LN(add[b][r][:] + rel_in[r][b][:]) * gamma + beta
// ---------------------------------------------------------------------------
__global__ __launch_bounds__(128) void residual_ln(
    const float* __restrict__ add, const float* __restrict__ rel_in,
    const float* __restrict__ gamma, const float* __restrict__ beta,
    float* __restrict__ out)
{
    const long idx = blockIdx.x;          // b*NR + r
    const long b = idx >> 11;
    const long r = idx & 2047;
    const int tid = threadIdx.x;
    const int f = tid * 4;

    const float4 a4 = *reinterpret_cast<const float4*>(&add[idx * DM + f]);
    const float4 r4 = *reinterpret_cast<const float4*>(&rel_in[(r * NB + b) * DM + f]);
    float x0 = a4.x + r4.x, x1 = a4.y + r4.y, x2 = a4.z + r4.z, x3 = a4.w + r4.w;

    float sum = x0 + x1 + x2 + x3;
    float ssq = x0 * x0 + x1 * x1 + x2 * x2 + x3 * x3;
    #pragma unroll
    for (int o = 16; o > 0; o >>= 1) {
        sum += __shfl_xor_sync(0xFFFFFFFFu, sum, o);
        ssq += __shfl_xor_sync(0xFFFFFFFFu, ssq, o);
    }
    __shared__ float s1[4], s2[4];
    const int w = tid >> 5;
    if ((tid & 31) == 0) { s1[w] = sum; s2[w] = ssq; }
    __syncthreads();
    sum = s1[0] + s1[1] + s1[2] + s1[3];
    ssq = s2[0] + s2[1] + s2[2] + s2[3];

    const float mean = sum * (1.f / DM);
    const float var = ssq * (1.f / DM) - mean * mean;
    const float rstd = rsqrtf(var + 1e-5f);

    const float4 g4 = *reinterpret_cast<const float4*>(&gamma[f]);
    const float4 be4 = *reinterpret_cast<const float4*>(&beta[f]);
    float4 o4;
    o4.x = (x0 - mean) * rstd * g4.x + be4.x;
    o4.y = (x1 - mean) * rstd * g4.y + be4.y;
    o4.z = (x2 - mean) * rstd * g4.z + be4.z;
    o4.w = (x3 - mean) * rstd * g4.w + be4.w;
    *reinterpret_cast<float4*>(&out[(r * NB + b) * DM + f]) = o4;
}

// ---------------------------------------------------------------------------
extern "C" void kernel_launch(void* const* d_in, const int* in_sizes, int n_in,
                              void* d_out, int out_size)
{
    const float* det_in = (const float*)d_in[0];
    const float* rel_in = (const float*)d_in[1];
    const float* W_det  = (const float*)d_in[2];
    const float* b_det  = (const float*)d_in[3];
    const float* W_rel  = (const float*)d_in[4];
    const float* b_rel  = (const float*)d_in[5];
    const float* W_val  = (const float*)d_in[6];
    const float* b_val  = (const float*)d_in[7];
    const float* gamma  = (const float*)d_in[8];
    const float* beta   = (const float*)d_in[9];
    float* out = (float*)d_out;

    __half *det16, *rel16, *wd16, *wr16, *wv16, *q16, *k16, *v16, *e16;
    float *s, *add, *inv;
    cudaGetSymbolAddress((void**)&det16, g_det16);
    cudaGetSymbolAddress((void**)&rel16, g_rel16);
    cudaGetSymbolAddress((void**)&wd16, g_wd16);
    cudaGetSymbolAddress((void**)&wr16, g_wr16);
    cudaGetSymbolAddress((void**)&wv16, g_wv16);
    cudaGetSymbolAddress((void**)&q16, g_q16);
    cudaGetSymbolAddress((void**)&k16, g_k16);
    cudaGetSymbolAddress((void**)&v16, g_v16);
    cudaGetSymbolAddress((void**)&e16, g_e16);
    cudaGetSymbolAddress((void**)&s, g_s);
    cudaGetSymbolAddress((void**)&add, g_add);
    cudaGetSymbolAddress((void**)&inv, g_inv);

    cudaFuncSetAttribute(hgemm<false, __half>, cudaFuncAttributeMaxDynamicSharedMemorySize, SMEM_BYTES);
    cudaFuncSetAttribute(hgemm<false, float>,  cudaFuncAttributeMaxDynamicSharedMemorySize, SMEM_BYTES);
    cudaFuncSetAttribute(hgemm<true, float>,   cudaFuncAttributeMaxDynamicSharedMemorySize, SMEM_BYTES);

    // Pass-through: out[0 : Nd*B*D] = det_in
    cudaMemcpyAsync(out, det_in, (size_t)ND * NB * DM * sizeof(float),
                    cudaMemcpyDeviceToDevice);

    // --- fp32 -> fp16 conversions
    cvt16<<<4096, 256>>>(det_in, det16, (long)ND * NB * DM);
    cvt16<<<4096, 256>>>(rel_in, rel16, (long)NR * NB * DM);
    cvt16<<<256, 256>>>(W_det, wd16, (long)DF * DM);
    cvt16<<<256, 256>>>(W_rel, wr16, (long)DF * DM);
    cvt16<<<256, 256>>>(W_val, wv16, (long)DF * DM);

    dim3 blk(512);

    // --- projections (NT): A rows = token (stride NB*DM halves), batch off DM
    dim3 gp(ND / 128, DF / 256, NB);
    hgemm<false, __half><<<gp, blk, SMEM_BYTES>>>(det16, wd16, q16, b_det, nullptr, 0,
        DM, (long)NB * DM, DM, DM, 0, DF, (long)ND * DF);
    hgemm<false, __half><<<gp, blk, SMEM_BYTES>>>(rel16, wr16, k16, b_rel, nullptr, 0,
        DM, (long)NB * DM, DM, DM, 0, DF, (long)NR * DF);
    hgemm<false, __half><<<gp, blk, SMEM_BYTES>>>(det16, wv16, v16, b_val, nullptr, 0,
        DM, (long)NB * DM, DM, DM, 0, DF, (long)ND * DF);

    // --- scores[b][r][d] = <rel_k[b][r], det_q[b][d]>  (NT, fp32 out)
    dim3 gs(NR / 128, ND / 256, NB);
    hgemm<false, float><<<gs, blk, SMEM_BYTES>>>(k16, q16, s, nullptr, nullptr, 0,
        DF, DF, (long)NR * DF, DF, (long)ND * DF, ND, (long)NR * ND);

    // --- exp (scaled) -> fp16 weights + 1/rowsum
    softmax_exp<<<NB * NR, 256>>>(s, e16, ND, 1.f / sqrtf((float)DF), inv);

    // --- rel_add[b][r][f] = (sum_d e * v) * inv[b][r]   (NN, fp32 out)
    dim3 ga(NR / 128, DF / 256, NB);
    hgemm<true, float><<<ga, blk, SMEM_BYTES>>>(e16, v16, add, nullptr, inv, NR,
        ND, ND, (long)NR * ND, DF, (long)ND * DF, DF, (long)NR * DF);

    // --- residual + LayerNorm -> out[Nd*B*D + ...]
    residual_ln<<<NB * NR, 128>>>(add, rel_in, gamma, beta,
                                  out + (size_t)ND * NB * DM);
}

// round 6
// speedup vs baseline: 5.2333x; 1.0259x over previous
#include <cuda_runtime.h>
#include <cuda_fp16.h>
#include <cstdint>
#include <math.h>

// ---------------------------------------------------------------------------
// InteractionLayer via fp16 mma.sync m16n8k16 + 3-stage cp.async + ldmatrix
// (arch-portable PTX; harness targets plain sm_103 — no 'a' features).
//   det_q/rel_k/det_v = proj(in) @ W^T + b        -> fp16
//   scores = rel_k @ det_q^T                      -> fp16 (store), fp32 accum
//   e = exp((scores - rowmax)/sqrt(F)) -> fp16;  inv = 1/rowsum (single pass)
//   rel_add = (e @ det_v) * inv                   -> fp32
//   out_rel = LN(rel_add + rel_in) * gamma + beta
// GEMM: CTA 128x256, 16 warps (2x8) of 64x32, BK=32, 3-stage cp.async.
// ---------------------------------------------------------------------------

#define ND 2048
#define NR 2048
#define NB 8
#define DM 512
#define DF 512

// scratch (no cudaMalloc allowed)
__device__ __align__(16) __half g_det16[(size_t)ND * NB * DM];
__device__ __align__(16) __half g_rel16[(size_t)NR * NB * DM];
__device__ __align__(16) __half g_wd16[(size_t)DF * DM];
__device__ __align__(16) __half g_wr16[(size_t)DF * DM];
__device__ __align__(16) __half g_wv16[(size_t)DF * DM];
__device__ __align__(16) __half g_q16[(size_t)NB * ND * DF];
__device__ __align__(16) __half g_k16[(size_t)NB * NR * DF];
__device__ __align__(16) __half g_v16[(size_t)NB * ND * DF];
__device__ __align__(16) __half g_s16[(size_t)NB * NR * ND];   // scores, then e
__device__ __align__(16) float  g_add[(size_t)NB * NR * DF];
__device__ float g_inv[(size_t)NB * NR];

__device__ __forceinline__ uint32_t smem_u32(const void* p) {
    uint32_t a;
    asm("{ .reg .u64 t; cvta.to.shared.u64 t, %1; cvt.u32.u64 %0, t; }" : "=r"(a) : "l"(p));
    return a;
}
__device__ __forceinline__ void cp16(uint32_t dst, const void* src) {
    asm volatile("cp.async.ca.shared.global [%0], [%1], 16;" :: "r"(dst), "l"(src) : "memory");
}
#define CP_COMMIT() asm volatile("cp.async.commit_group;" ::: "memory")

__device__ __forceinline__ void ldsm4(uint32_t* r, uint32_t a) {
    asm volatile("ldmatrix.sync.aligned.m8n8.x4.shared.b16 {%0,%1,%2,%3}, [%4];"
                 : "=r"(r[0]), "=r"(r[1]), "=r"(r[2]), "=r"(r[3]) : "r"(a));
}
__device__ __forceinline__ void ldsm4t(uint32_t* r, uint32_t a) {
    asm volatile("ldmatrix.sync.aligned.m8n8.x4.trans.shared.b16 {%0,%1,%2,%3}, [%4];"
                 : "=r"(r[0]), "=r"(r[1]), "=r"(r[2]), "=r"(r[3]) : "r"(a));
}

// smem halves per buffer (30720 B): As 128x40 (10240 B), Bs 20480 B
// (NT: 256x40; NN: 32x264). THREE buffers: 92160 B.
#define AS_STRIDE 40
#define BNT_STRIDE 40
#define BNN_STRIDE 264
#define BUF_BYTES 30720
#define NSTAGE 3
#define SMEM_BYTES (NSTAGE * BUF_BYTES)

// ---------------------------------------------------------------------------
// BNN=false (NT): C[m,n] = sum_k A[m*rsA+k] * B[n*rsB+k]
// BNN=true  (NN): C[m,n] = sum_k A[m*rsA+k] * B[k*rsB+n]
// ---------------------------------------------------------------------------
template <bool BNN, typename OutT>
__global__ __launch_bounds__(512, 1) void hgemm(
    const __half* __restrict__ A, const __half* __restrict__ B, OutT* __restrict__ C,
    const float* __restrict__ bias, const float* __restrict__ rowScale, long ssS,
    int K, long rsA, long bsA, long rsB, long bsB, long rsC, long bsC)
{
    extern __shared__ __align__(16) char dyn[];
    const uint32_t sb = smem_u32(dyn);

    const int tid = threadIdx.x;
    const int wid = tid >> 5;
    const int lane = tid & 31;
    const int g = lane >> 2;
    const int c = lane & 3;
    const int t8 = lane >> 3;
    const int lr = lane & 7;
    const int wm = (wid >> 3) * 64;
    const int wn = (wid & 7) * 32;

    const long rowBase = (long)blockIdx.x * 128;
    const long colBase = (long)blockIdx.y * 256;
    A += (long)blockIdx.z * bsA;
    B += (long)blockIdx.z * bsB;
    C += (long)blockIdx.z * bsC;

    float acc[4][4][4];
    #pragma unroll
    for (int mt = 0; mt < 4; mt++)
        #pragma unroll
        for (int nt = 0; nt < 4; nt++)
            #pragma unroll
            for (int r = 0; r < 4; r++) acc[mt][nt][r] = 0.f;

    const int NS = K / 32;

    auto issue = [&](int s) {
        const int buf = s % NSTAGE;
        const long k0 = (long)s * 32;
        const uint32_t ab = sb + buf * BUF_BYTES;
        const uint32_t bb = ab + 10240;
        {   // A: 128 rows x 4 chunks
            const int row = tid >> 2, ch = tid & 3;
            cp16(ab + (row * AS_STRIDE + ch * 8) * 2,
                 &A[(rowBase + row) * rsA + k0 + ch * 8]);
        }
        if (BNN) {                      // B: 32 k-rows x 32 chunks
            #pragma unroll
            for (int i = 0; i < 2; i++) {
                const int idx = i * 512 + tid;
                const int kr = idx >> 5, ch = idx & 31;
                cp16(bb + (kr * BNN_STRIDE + ch * 8) * 2,
                     &B[(k0 + kr) * rsB + colBase + ch * 8]);
            }
        } else {                        // B: 256 rows x 4 chunks
            #pragma unroll
            for (int i = 0; i < 2; i++) {
                const int idx = i * 512 + tid;
                const int row = idx >> 2, ch = idx & 3;
                cp16(bb + (row * BNT_STRIDE + ch * 8) * 2,
                     &B[(colBase + row) * rsB + k0 + ch * 8]);
            }
        }
        CP_COMMIT();
    };

    issue(0);
    if (NS > 1) issue(1);
    if (NS > 2) issue(2);

    for (int s = 0; s < NS; s++) {
        if (s + 3 <= NS)
            asm volatile("cp.async.wait_group 2;" ::: "memory");
        else if (s + 2 == NS)
            asm volatile("cp.async.wait_group 1;" ::: "memory");
        else
            asm volatile("cp.async.wait_group 0;" ::: "memory");
        __syncthreads();

        const uint32_t ab = sb + (s % NSTAGE) * BUF_BYTES;
        const uint32_t bb = ab + 10240;

        #pragma unroll
        for (int kk = 0; kk < 2; kk++) {
            const int k0h = kk * 16;
            uint32_t a[4][4];
            #pragma unroll
            for (int mt = 0; mt < 4; mt++)
                ldsm4(a[mt], ab + ((wm + mt * 16 + (t8 & 1) * 8 + lr) * AS_STRIDE
                                   + k0h + (t8 >> 1) * 8) * 2);
            uint32_t b[2][4];
            #pragma unroll
            for (int np = 0; np < 2; np++) {
                if (BNN)
                    ldsm4t(b[np], bb + ((k0h + (t8 & 1) * 8 + lr) * BNN_STRIDE
                                        + wn + np * 16 + (t8 >> 1) * 8) * 2);
                else
                    ldsm4(b[np], bb + ((wn + np * 16 + (t8 >> 1) * 8 + lr) * BNT_STRIDE
                                       + k0h + (t8 & 1) * 8) * 2);
            }
            #pragma unroll
            for (int mt = 0; mt < 4; mt++)
                #pragma unroll
                for (int nt = 0; nt < 4; nt++)
                    asm volatile(
                        "mma.sync.aligned.m16n8k16.row.col.f32.f16.f16.f32 "
                        "{%0,%1,%2,%3}, {%4,%5,%6,%7}, {%8,%9}, {%0,%1,%2,%3};"
                        : "+f"(acc[mt][nt][0]), "+f"(acc[mt][nt][1]),
                          "+f"(acc[mt][nt][2]), "+f"(acc[mt][nt][3])
                        : "r"(a[mt][0]), "r"(a[mt][1]), "r"(a[mt][2]), "r"(a[mt][3]),
                          "r"(b[nt >> 1][(nt & 1) * 2]), "r"(b[nt >> 1][(nt & 1) * 2 + 1]));
        }
        __syncthreads();
        if (s + 3 < NS) issue(s + 3);
    }

    // ---- epilogue
    #pragma unroll
    for (int mt = 0; mt < 4; mt++) {
        const long row0 = rowBase + wm + mt * 16 + g;
        float sc0 = 1.f, sc1 = 1.f;
        if (rowScale) {
            sc0 = rowScale[(long)blockIdx.z * ssS + row0];
            sc1 = rowScale[(long)blockIdx.z * ssS + row0 + 8];
        }
        #pragma unroll
        for (int nt = 0; nt < 4; nt++) {
            const long col = colBase + wn + nt * 8 + 2 * c;
            float bx = 0.f, by = 0.f;
            if (bias) { bx = bias[col]; by = bias[col + 1]; }
            float x0 = acc[mt][nt][0] * sc0 + bx, x1 = acc[mt][nt][1] * sc0 + by;
            float x2 = acc[mt][nt][2] * sc1 + bx, x3 = acc[mt][nt][3] * sc1 + by;
            if (sizeof(OutT) == 2) {
                *reinterpret_cast<__half2*>(C + row0 * rsC + col) = __floats2half2_rn(x0, x1);
                *reinterpret_cast<__half2*>(C + (row0 + 8) * rsC + col) = __floats2half2_rn(x2, x3);
            } else {
                *reinterpret_cast<float2*>((float*)C + row0 * rsC + col) = make_float2(x0, x1);
                *reinterpret_cast<float2*>((float*)C + (row0 + 8) * rsC + col) = make_float2(x2, x3);
            }
        }
    }
}

// ---------------------------------------------------------------------------
// fp32 -> fp16 conversion; optionally also copy fp32 to `copy` (pass-through).
// ---------------------------------------------------------------------------
__global__ __launch_bounds__(256) void cvt16(const float* __restrict__ src,
                                             __half* __restrict__ dst,
                                             float* __restrict__ copy, long n)
{
    long i = ((long)blockIdx.x * blockDim.x + threadIdx.x) * 4;
    const long stride = (long)gridDim.x * blockDim.x * 4;
    for (; i < n; i += stride) {
        float4 v = *reinterpret_cast<const float4*>(src + i);
        __half2* p = reinterpret_cast<__half2*>(dst + i);
        p[0] = __floats2half2_rn(v.x, v.y);
        p[1] = __floats2half2_rn(v.z, v.w);
        if (copy) *reinterpret_cast<float4*>(copy + i) = v;
    }
}

// ---------------------------------------------------------------------------
// Single-pass softmax on fp16 scores (cols == 2048 == 256 thr * 8 vals):
// e = exp((s - rowmax)*scale) fp16 in place; inv[row] = 1/rowsum.
// ---------------------------------------------------------------------------
__global__ __launch_bounds__(256) void softmax_exp(
    __half* __restrict__ S, float scale, float* __restrict__ inv)
{
    __half* p = S + (long)blockIdx.x * 2048;
    const int tid = threadIdx.x;
    __shared__ float red[256];

    // load 8 halves
    uint4 raw = *reinterpret_cast<const uint4*>(p + tid * 8);
    const __half2* h = reinterpret_cast<const __half2*>(&raw);
    float x[8];
    #pragma unroll
    for (int i = 0; i < 4; i++) {
        float2 f = __half22float2(h[i]);
        x[2 * i] = f.x; x[2 * i + 1] = f.y;
    }

    float m = x[0];
    #pragma unroll
    for (int i = 1; i < 8; i++) m = fmaxf(m, x[i]);
    red[tid] = m; __syncthreads();
    for (int s = 128; s > 0; s >>= 1) {
        if (tid < s) red[tid] = fmaxf(red[tid], red[tid + s]);
        __syncthreads();
    }
    m = red[0];
    __syncthreads();

    float e[8], sum = 0.f;
    #pragma unroll
    for (int i = 0; i < 8; i++) {
        e[i] = __expf((x[i] - m) * scale);
        sum += e[i];
    }
    uint4 outw;
    __half2* ho = reinterpret_cast<__half2*>(&outw);
    #pragma unroll
    for (int i = 0; i < 4; i++)
        ho[i] = __floats2half2_rn(e[2 * i], e[2 * i + 1]);
    *reinterpret_cast<uint4*>(p + tid * 8) = outw;

    red[tid] = sum; __syncthreads();
    for (int s = 128; s > 0; s >>= 1) {
        if (tid < s) red[tid] += red[tid + s];
        __syncthreads();
    }
    if (tid == 0) inv[blockIdx.x] = 1.f / red[0];
}

// ---------------------------------------------------------------------------
// out[r][b][:] = LN(add[b][r][:] + rel_in[r][b][:]) * gamma + beta
// ---------------------------------------------------------------------------
__global__ __launch_bounds__(128) void residual_ln(
    const float* __restrict__ add, const float* __restrict__ rel_in,
    const float* __restrict__ gamma, const float* __restrict__ beta,
    float* __restrict__ out)
{
    const long idx = blockIdx.x;          // b*NR + r
    const long b = idx >> 11;
    const long r = idx & 2047;
    const int tid = threadIdx.x;
    const int f = tid * 4;

    const float4 a4 = *reinterpret_cast<const float4*>(&add[idx * DM + f]);
    const float4 r4 = *reinterpret_cast<const float4*>(&rel_in[(r * NB + b) * DM + f]);
    float x0 = a4.x + r4.x, x1 = a4.y + r4.y, x2 = a4.z + r4.z, x3 = a4.w + r4.w;

    float sum = x0 + x1 + x2 + x3;
    float ssq = x0 * x0 + x1 * x1 + x2 * x2 + x3 * x3;
    #pragma unroll
    for (int o = 16; o > 0; o >>= 1) {
        sum += __shfl_xor_sync(0xFFFFFFFFu, sum, o);
        ssq += __shfl_xor_sync(0xFFFFFFFFu, ssq, o);
    }
    __shared__ float s1[4], s2[4];
    const int w = tid >> 5;
    if ((tid & 31) == 0) { s1[w] = sum; s2[w] = ssq; }
    __syncthreads();
    sum = s1[0] + s1[1] + s1[2] + s1[3];
    ssq = s2[0] + s2[1] + s2[2] + s2[3];

    const float mean = sum * (1.f / DM);
    const float var = ssq * (1.f / DM) - mean * mean;
    const float rstd = rsqrtf(var + 1e-5f);

    const float4 g4 = *reinterpret_cast<const float4*>(&gamma[f]);
    const float4 be4 = *reinterpret_cast<const float4*>(&beta[f]);
    float4 o4;
    o4.x = (x0 - mean) * rstd * g4.x + be4.x;
    o4.y = (x1 - mean) * rstd * g4.y + be4.y;
    o4.z = (x2 - mean) * rstd * g4.z + be4.z;
    o4.w = (x3 - mean) * rstd * g4.w + be4.w;
    *reinterpret_cast<float4*>(&out[(r * NB + b) * DM + f]) = o4;
}

// ---------------------------------------------------------------------------
extern "C" void kernel_launch(void* const* d_in, const int* in_sizes, int n_in,
                              void* d_out, int out_size)
{
    const float* det_in = (const float*)d_in[0];
    const float* rel_in = (const float*)d_in[1];
    const float* W_det  = (const float*)d_in[2];
    const float* b_det  = (const float*)d_in[3];
    const float* W_rel  = (const float*)d_in[4];
    const float* b_rel  = (const float*)d_in[5];
    const float* W_val  = (const float*)d_in[6];
    const float* b_val  = (const float*)d_in[7];
    const float* gamma  = (const float*)d_in[8];
    const float* beta   = (const float*)d_in[9];
    float* out = (float*)d_out;

    __half *det16, *rel16, *wd16, *wr16, *wv16, *q16, *k16, *v16, *s16;
    float *add, *inv;
    cudaGetSymbolAddress((void**)&det16, g_det16);
    cudaGetSymbolAddress((void**)&rel16, g_rel16);
    cudaGetSymbolAddress((void**)&wd16, g_wd16);
    cudaGetSymbolAddress((void**)&wr16, g_wr16);
    cudaGetSymbolAddress((void**)&wv16, g_wv16);
    cudaGetSymbolAddress((void**)&q16, g_q16);
    cudaGetSymbolAddress((void**)&k16, g_k16);
    cudaGetSymbolAddress((void**)&v16, g_v16);
    cudaGetSymbolAddress((void**)&s16, g_s16);
    cudaGetSymbolAddress((void**)&add, g_add);
    cudaGetSymbolAddress((void**)&inv, g_inv);

    cudaFuncSetAttribute(hgemm<false, __half>, cudaFuncAttributeMaxDynamicSharedMemorySize, SMEM_BYTES);
    cudaFuncSetAttribute(hgemm<true, float>,   cudaFuncAttributeMaxDynamicSharedMemorySize, SMEM_BYTES);

    // --- fp32 -> fp16 conversions (det conversion also emits the pass-through)
    cvt16<<<4096, 256>>>(det_in, det16, out, (long)ND * NB * DM);
    cvt16<<<4096, 256>>>(rel_in, rel16, nullptr, (long)NR * NB * DM);
    cvt16<<<256, 256>>>(W_det, wd16, nullptr, (long)DF * DM);
    cvt16<<<256, 256>>>(W_rel, wr16, nullptr, (long)DF * DM);
    cvt16<<<256, 256>>>(W_val, wv16, nullptr, (long)DF * DM);

    dim3 blk(512);

    // --- projections (NT)
    dim3 gp(ND / 128, DF / 256, NB);
    hgemm<false, __half><<<gp, blk, SMEM_BYTES>>>(det16, wd16, q16, b_det, nullptr, 0,
        DM, (long)NB * DM, DM, DM, 0, DF, (long)ND * DF);
    hgemm<false, __half><<<gp, blk, SMEM_BYTES>>>(rel16, wr16, k16, b_rel, nullptr, 0,
        DM, (long)NB * DM, DM, DM, 0, DF, (long)NR * DF);
    hgemm<false, __half><<<gp, blk, SMEM_BYTES>>>(det16, wv16, v16, b_val, nullptr, 0,
        DM, (long)NB * DM, DM, DM, 0, DF, (long)ND * DF);

    // --- scores (NT, fp16 out)
    dim3 gs(NR / 128, ND / 256, NB);
    hgemm<false, __half><<<gs, blk, SMEM_BYTES>>>(k16, q16, s16, nullptr, nullptr, 0,
        DF, DF, (long)NR * DF, DF, (long)ND * DF, ND, (long)NR * ND);

    // --- single-pass exp + 1/rowsum (normalization folded into AV epilogue)
    softmax_exp<<<NB * NR, 256>>>(s16, 1.f / sqrtf((float)DF), inv);

    // --- rel_add = (e @ v) * inv   (NN, fp32 out)
    dim3 ga(NR / 128, DF / 256, NB);
    hgemm<true, float><<<ga, blk, SMEM_BYTES>>>(s16, v16, add, nullptr, inv, NR,
        ND, ND, (long)NR * ND, DF, (long)ND * DF, DF, (long)NR * DF);

    // --- residual + LayerNorm -> out[Nd*B*D + ...]
    residual_ln<<<NB * NR, 128>>>(add, rel_in, gamma, beta,
                                  out + (size_t)ND * NB * DM);
}

// round 7
// speedup vs baseline: 6.0325x; 1.1527x over previous
#include <cuda_runtime.h>
#include <cuda_fp16.h>
#include <cstdint>
#include <math.h>

// ---------------------------------------------------------------------------
// InteractionLayer via fp16 mma.sync m16n8k16 + 4-stage cp.async + ldmatrix
// (arch-portable PTX; harness targets plain sm_103 — no 'a' features).
// GEMM: CTA 128x256, 8 warps (2x4) of 64x64, BK=32, 4-stage cp.async,
// single __syncthreads per slab (4 buffers make the trailing barrier redundant).
// ---------------------------------------------------------------------------

#define ND 2048
#define NR 2048
#define NB 8
#define DM 512
#define DF 512

// scratch (no cudaMalloc allowed)
__device__ __align__(16) __half g_det16[(size_t)ND * NB * DM];
__device__ __align__(16) __half g_rel16[(size_t)NR * NB * DM];
__device__ __align__(16) __half g_wd16[(size_t)DF * DM];
__device__ __align__(16) __half g_wr16[(size_t)DF * DM];
__device__ __align__(16) __half g_wv16[(size_t)DF * DM];
__device__ __align__(16) __half g_q16[(size_t)NB * ND * DF];
__device__ __align__(16) __half g_k16[(size_t)NB * NR * DF];
__device__ __align__(16) __half g_v16[(size_t)NB * ND * DF];
__device__ __align__(16) __half g_s16[(size_t)NB * NR * ND];   // scores, then e
__device__ __align__(16) float  g_add[(size_t)NB * NR * DF];
__device__ float g_inv[(size_t)NB * NR];

__device__ __forceinline__ uint32_t smem_u32(const void* p) {
    uint32_t a;
    asm("{ .reg .u64 t; cvta.to.shared.u64 t, %1; cvt.u32.u64 %0, t; }" : "=r"(a) : "l"(p));
    return a;
}
__device__ __forceinline__ void cp16(uint32_t dst, const void* src) {
    asm volatile("cp.async.ca.shared.global [%0], [%1], 16;" :: "r"(dst), "l"(src) : "memory");
}
#define CP_COMMIT() asm volatile("cp.async.commit_group;" ::: "memory")

__device__ __forceinline__ void ldsm4(uint32_t* r, uint32_t a) {
    asm volatile("ldmatrix.sync.aligned.m8n8.x4.shared.b16 {%0,%1,%2,%3}, [%4];"
                 : "=r"(r[0]), "=r"(r[1]), "=r"(r[2]), "=r"(r[3]) : "r"(a));
}
__device__ __forceinline__ void ldsm4t(uint32_t* r, uint32_t a) {
    asm volatile("ldmatrix.sync.aligned.m8n8.x4.trans.shared.b16 {%0,%1,%2,%3}, [%4];"
                 : "=r"(r[0]), "=r"(r[1]), "=r"(r[2]), "=r"(r[3]) : "r"(a));
}

// smem halves per buffer (30720 B): As 128x40 (10240 B), Bs 20480 B
// (NT: 256x40; NN: 32x264). FOUR buffers: 122880 B.
#define AS_STRIDE 40
#define BNT_STRIDE 40
#define BNN_STRIDE 264
#define BUF_BYTES 30720
#define NSTAGE 4
#define SMEM_BYTES (NSTAGE * BUF_BYTES)

// ---------------------------------------------------------------------------
// Core GEMM body. 256 threads, 8 warps (2x4), warp tile 64x64, CTA 128x256.
// BNN=false (NT): C[m,n] = sum_k A[m*rsA+k] * B[n*rsB+k]
// BNN=true  (NN): C[m,n] = sum_k A[m*rsA+k] * B[k*rsB+n]
// A,B,C already batch-offset by caller.
// ---------------------------------------------------------------------------
template <bool BNN, typename OutT>
__device__ __forceinline__ void gemm_body(
    const __half* __restrict__ A, const __half* __restrict__ B, OutT* __restrict__ C,
    const float* __restrict__ bias, const float* __restrict__ rowScale,
    int K, long rsA, long rsB, long rsC)
{
    extern __shared__ __align__(16) char dyn[];
    const uint32_t sb = smem_u32(dyn);

    const int tid = threadIdx.x;
    const int wid = tid >> 5;
    const int lane = tid & 31;
    const int g = lane >> 2;
    const int c = lane & 3;
    const int t8 = lane >> 3;
    const int lr = lane & 7;
    const int wm = (wid >> 2) * 64;     // warp m: 0/64
    const int wn = (wid & 3) * 64;      // warp n: 0..192

    const long rowBase = (long)blockIdx.x * 128;
    const long colBase = (long)blockIdx.y * 256;

    float acc[4][8][4];
    #pragma unroll
    for (int mt = 0; mt < 4; mt++)
        #pragma unroll
        for (int nt = 0; nt < 8; nt++)
            #pragma unroll
            for (int r = 0; r < 4; r++) acc[mt][nt][r] = 0.f;

    const int NS = K / 32;

    auto issue = [&](int s) {
        const int buf = s % NSTAGE;
        const long k0 = (long)s * 32;
        const uint32_t ab = sb + buf * BUF_BYTES;
        const uint32_t bb = ab + 10240;
        #pragma unroll
        for (int i = 0; i < 2; i++) {   // A: 128 rows x 4 chunks = 512 cp16
            const int idx = i * 256 + tid;
            const int row = idx >> 2, ch = idx & 3;
            cp16(ab + (row * AS_STRIDE + ch * 8) * 2,
                 &A[(rowBase + row) * rsA + k0 + ch * 8]);
        }
        if (BNN) {                      // B: 32 k-rows x 32 chunks = 1024 cp16
            #pragma unroll
            for (int i = 0; i < 4; i++) {
                const int idx = i * 256 + tid;
                const int kr = idx >> 5, ch = idx & 31;
                cp16(bb + (kr * BNN_STRIDE + ch * 8) * 2,
                     &B[(k0 + kr) * rsB + colBase + ch * 8]);
            }
        } else {                        // B: 256 rows x 4 chunks = 1024 cp16
            #pragma unroll
            for (int i = 0; i < 4; i++) {
                const int idx = i * 256 + tid;
                const int row = idx >> 2, ch = idx & 3;
                cp16(bb + (row * BNT_STRIDE + ch * 8) * 2,
                     &B[(colBase + row) * rsB + k0 + ch * 8]);
            }
        }
        CP_COMMIT();
    };

    issue(0);
    if (NS > 1) issue(1);
    if (NS > 2) issue(2);

    for (int s = 0; s < NS; s++) {
        if (s + 3 <= NS)
            asm volatile("cp.async.wait_group 2;" ::: "memory");
        else if (s + 2 == NS)
            asm volatile("cp.async.wait_group 1;" ::: "memory");
        else
            asm volatile("cp.async.wait_group 0;" ::: "memory");
        __syncthreads();   // single barrier per slab (4 buffers -> no trailing one)

        const uint32_t ab = sb + (s % NSTAGE) * BUF_BYTES;
        const uint32_t bb = ab + 10240;

        #pragma unroll
        for (int kk = 0; kk < 2; kk++) {
            const int k0h = kk * 16;
            uint32_t a[4][4];
            #pragma unroll
            for (int mt = 0; mt < 4; mt++)
                ldsm4(a[mt], ab + ((wm + mt * 16 + (t8 & 1) * 8 + lr) * AS_STRIDE
                                   + k0h + (t8 >> 1) * 8) * 2);
            uint32_t b[4][4];
            #pragma unroll
            for (int np = 0; np < 4; np++) {
                if (BNN)
                    ldsm4t(b[np], bb + ((k0h + (t8 & 1) * 8 + lr) * BNN_STRIDE
                                        + wn + np * 16 + (t8 >> 1) * 8) * 2);
                else
                    ldsm4(b[np], bb + ((wn + np * 16 + (t8 >> 1) * 8 + lr) * BNT_STRIDE
                                       + k0h + (t8 & 1) * 8) * 2);
            }
            #pragma unroll
            for (int mt = 0; mt < 4; mt++)
                #pragma unroll
                for (int nt = 0; nt < 8; nt++)
                    asm volatile(
                        "mma.sync.aligned.m16n8k16.row.col.f32.f16.f16.f32 "
                        "{%0,%1,%2,%3}, {%4,%5,%6,%7}, {%8,%9}, {%0,%1,%2,%3};"
                        : "+f"(acc[mt][nt][0]), "+f"(acc[mt][nt][1]),
                          "+f"(acc[mt][nt][2]), "+f"(acc[mt][nt][3])
                        : "r"(a[mt][0]), "r"(a[mt][1]), "r"(a[mt][2]), "r"(a[mt][3]),
                          "r"(b[nt >> 1][(nt & 1) * 2]), "r"(b[nt >> 1][(nt & 1) * 2 + 1]));
        }
        if (s + 3 < NS) issue(s + 3);
    }

    // ---- epilogue
    #pragma unroll
    for (int mt = 0; mt < 4; mt++) {
        const long row0 = rowBase + wm + mt * 16 + g;
        float sc0 = 1.f, sc1 = 1.f;
        if (rowScale) {
            sc0 = rowScale[row0];
            sc1 = rowScale[row0 + 8];
        }
        #pragma unroll
        for (int nt = 0; nt < 8; nt++) {
            const long col = colBase + wn + nt * 8 + 2 * c;
            float bx = 0.f, by = 0.f;
            if (bias) { bx = bias[col]; by = bias[col + 1]; }
            float x0 = acc[mt][nt][0] * sc0 + bx, x1 = acc[mt][nt][1] * sc0 + by;
            float x2 = acc[mt][nt][2] * sc1 + bx, x3 = acc[mt][nt][3] * sc1 + by;
            if (sizeof(OutT) == 2) {
                *reinterpret_cast<__half2*>(C + row0 * rsC + col) = __floats2half2_rn(x0, x1);
                *reinterpret_cast<__half2*>(C + (row0 + 8) * rsC + col) = __floats2half2_rn(x2, x3);
            } else {
                *reinterpret_cast<float2*>((float*)C + row0 * rsC + col) = make_float2(x0, x1);
                *reinterpret_cast<float2*>((float*)C + (row0 + 8) * rsC + col) = make_float2(x2, x3);
            }
        }
    }
}

// Generic batched wrapper.
template <bool BNN, typename OutT>
__global__ __launch_bounds__(256, 1) void hgemm(
    const __half* __restrict__ A, const __half* __restrict__ B, OutT* __restrict__ C,
    const float* __restrict__ bias, const float* __restrict__ rowScale, long ssS,
    int K, long rsA, long bsA, long rsB, long bsB, long rsC, long bsC)
{
    const int bz = blockIdx.z;
    gemm_body<BNN, OutT>(A + (long)bz * bsA, B + (long)bz * bsB, C + (long)bz * bsC,
                         bias, rowScale ? rowScale + (long)bz * ssS : nullptr,
                         K, rsA, rsB, rsC);
}

// Merged projection launch: z = which*NB + b; which: 0->det_q, 1->rel_k, 2->det_v.
__global__ __launch_bounds__(256, 1) void hgemm_proj(
    const __half* __restrict__ det16, const __half* __restrict__ rel16,
    const __half* __restrict__ wd, const __half* __restrict__ wr, const __half* __restrict__ wv,
    const float* __restrict__ bd, const float* __restrict__ br, const float* __restrict__ bv,
    __half* __restrict__ q16, __half* __restrict__ k16, __half* __restrict__ v16)
{
    const int z = blockIdx.z;
    const int which = z >> 3;
    const int b = z & 7;
    const __half* A = (which == 1) ? rel16 : det16;
    const __half* W = (which == 0) ? wd : (which == 1) ? wr : wv;
    const float* bias = (which == 0) ? bd : (which == 1) ? br : bv;
    __half* C = (which == 0) ? q16 : (which == 1) ? k16 : v16;
    gemm_body<false, __half>(A + (long)b * DM, W, C + (long)b * ND * DF,
                             bias, nullptr, DM, (long)NB * DM, DM, DF);
}

// ---------------------------------------------------------------------------
// fp32 -> fp16 conversion; optionally also copy fp32 to `copy` (pass-through).
// ---------------------------------------------------------------------------
__global__ __launch_bounds__(256) void cvt16(const float* __restrict__ src,
                                             __half* __restrict__ dst,
                                             float* __restrict__ copy, long n)
{
    long i = ((long)blockIdx.x * blockDim.x + threadIdx.x) * 4;
    const long stride = (long)gridDim.x * blockDim.x * 4;
    for (; i < n; i += stride) {
        float4 v = *reinterpret_cast<const float4*>(src + i);
        __half2* p = reinterpret_cast<__half2*>(dst + i);
        p[0] = __floats2half2_rn(v.x, v.y);
        p[1] = __floats2half2_rn(v.z, v.w);
        if (copy) *reinterpret_cast<float4*>(copy + i) = v;
    }
}

// ---------------------------------------------------------------------------
// Single-pass softmax on fp16 scores (2048 cols = 256 thr x 8 vals):
// e = exp((s - rowmax)*scale) fp16 in place; inv[row] = 1/rowsum.
// ---------------------------------------------------------------------------
__global__ __launch_bounds__(256) void softmax_exp(
    __half* __restrict__ S, float scale, float* __restrict__ inv)
{
    __half* p = S + (long)blockIdx.x * 2048;
    const int tid = threadIdx.x;
    __shared__ float red[256];

    uint4 raw = *reinterpret_cast<const uint4*>(p + tid * 8);
    const __half2* h = reinterpret_cast<const __half2*>(&raw);
    float x[8];
    #pragma unroll
    for (int i = 0; i < 4; i++) {
        float2 f = __half22float2(h[i]);
        x[2 * i] = f.x; x[2 * i + 1] = f.y;
    }

    float m = x[0];
    #pragma unroll
    for (int i = 1; i < 8; i++) m = fmaxf(m, x[i]);
    red[tid] = m; __syncthreads();
    for (int s = 128; s > 0; s >>= 1) {
        if (tid < s) red[tid] = fmaxf(red[tid], red[tid + s]);
        __syncthreads();
    }
    m = red[0];
    __syncthreads();

    float e[8], sum = 0.f;
    #pragma unroll
    for (int i = 0; i < 8; i++) {
        e[i] = __expf((x[i] - m) * scale);
        sum += e[i];
    }
    uint4 outw;
    __half2* ho = reinterpret_cast<__half2*>(&outw);
    #pragma unroll
    for (int i = 0; i < 4; i++)
        ho[i] = __floats2half2_rn(e[2 * i], e[2 * i + 1]);
    *reinterpret_cast<uint4*>(p + tid * 8) = outw;

    red[tid] = sum; __syncthreads();
    for (int s = 128; s > 0; s >>= 1) {
        if (tid < s) red[tid] += red[tid + s];
        __syncthreads();
    }
    if (tid == 0) inv[blockIdx.x] = 1.f / red[0];
}

// ---------------------------------------------------------------------------
// out[r][b][:] = LN(add[b][r][:] + rel_in[r][b][:]) * gamma + beta
// ---------------------------------------------------------------------------
__global__ __launch_bounds__(128) void residual_ln(
    const float* __restrict__ add, const float* __restrict__ rel_in,
    const float* __restrict__ gamma, const float* __restrict__ beta,
    float* __restrict__ out)
{
    const long idx = blockIdx.x;          // b*NR + r
    const long b = idx >> 11;
    const long r = idx & 2047;
    const int tid = threadIdx.x;
    const int f = tid * 4;

    const float4 a4 = *reinterpret_cast<const float4*>(&add[idx * DM + f]);
    const float4 r4 = *reinterpret_cast<const float4*>(&rel_in[(r * NB + b) * DM + f]);
    float x0 = a4.x + r4.x, x1 = a4.y + r4.y, x2 = a4.z + r4.z, x3 = a4.w + r4.w;

    float sum = x0 + x1 + x2 + x3;
    float ssq = x0 * x0 + x1 * x1 + x2 * x2 + x3 * x3;
    #pragma unroll
    for (int o = 16; o > 0; o >>= 1) {
        sum += __shfl_xor_sync(0xFFFFFFFFu, sum, o);
        ssq += __shfl_xor_sync(0xFFFFFFFFu, ssq, o);
    }
    __shared__ float s1[4], s2[4];
    const int w = tid >> 5;
    if ((tid & 31) == 0) { s1[w] = sum; s2[w] = ssq; }
    __syncthreads();
    sum = s1[0] + s1[1] + s1[2] + s1[3];
    ssq = s2[0] + s2[1] + s2[2] + s2[3];

    const float mean = sum * (1.f / DM);
    const float var = ssq * (1.f / DM) - mean * mean;
    const float rstd = rsqrtf(var + 1e-5f);

    const float4 g4 = *reinterpret_cast<const float4*>(&gamma[f]);
    const float4 be4 = *reinterpret_cast<const float4*>(&beta[f]);
    float4 o4;
    o4.x = (x0 - mean) * rstd * g4.x + be4.x;
    o4.y = (x1 - mean) * rstd * g4.y + be4.y;
    o4.z = (x2 - mean) * rstd * g4.z + be4.z;
    o4.w = (x3 - mean) * rstd * g4.w + be4.w;
    *reinterpret_cast<float4*>(&out[(r * NB + b) * DM + f]) = o4;
}

// ---------------------------------------------------------------------------
extern "C" void kernel_launch(void* const* d_in, const int* in_sizes, int n_in,
                              void* d_out, int out_size)
{
    const float* det_in = (const float*)d_in[0];
    const float* rel_in = (const float*)d_in[1];
    const float* W_det  = (const float*)d_in[2];
    const float* b_det  = (const float*)d_in[3];
    const float* W_rel  = (const float*)d_in[4];
    const float* b_rel  = (const float*)d_in[5];
    const float* W_val  = (const float*)d_in[6];
    const float* b_val  = (const float*)d_in[7];
    const float* gamma  = (const float*)d_in[8];
    const float* beta   = (const float*)d_in[9];
    float* out = (float*)d_out;

    __half *det16, *rel16, *wd16, *wr16, *wv16, *q16, *k16, *v16, *s16;
    float *add, *inv;
    cudaGetSymbolAddress((void**)&det16, g_det16);
    cudaGetSymbolAddress((void**)&rel16, g_rel16);
    cudaGetSymbolAddress((void**)&wd16, g_wd16);
    cudaGetSymbolAddress((void**)&wr16, g_wr16);
    cudaGetSymbolAddress((void**)&wv16, g_wv16);
    cudaGetSymbolAddress((void**)&q16, g_q16);
    cudaGetSymbolAddress((void**)&k16, g_k16);
    cudaGetSymbolAddress((void**)&v16, g_v16);
    cudaGetSymbolAddress((void**)&s16, g_s16);
    cudaGetSymbolAddress((void**)&add, g_add);
    cudaGetSymbolAddress((void**)&inv, g_inv);

    cudaFuncSetAttribute(hgemm_proj, cudaFuncAttributeMaxDynamicSharedMemorySize, SMEM_BYTES);
    cudaFuncSetAttribute(hgemm<false, __half>, cudaFuncAttributeMaxDynamicSharedMemorySize, SMEM_BYTES);
    cudaFuncSetAttribute(hgemm<true, float>,   cudaFuncAttributeMaxDynamicSharedMemorySize, SMEM_BYTES);

    // --- fp32 -> fp16 conversions (det conversion also emits the pass-through)
    cvt16<<<4096, 256>>>(det_in, det16, out, (long)ND * NB * DM);
    cvt16<<<4096, 256>>>(rel_in, rel16, nullptr, (long)NR * NB * DM);
    cvt16<<<256, 256>>>(W_det, wd16, nullptr, (long)DF * DM);
    cvt16<<<256, 256>>>(W_rel, wr16, nullptr, (long)DF * DM);
    cvt16<<<256, 256>>>(W_val, wv16, nullptr, (long)DF * DM);

    dim3 blk(256);

    // --- all three projections in ONE launch (768 CTAs)
    dim3 gp(ND / 128, DF / 256, 3 * NB);
    hgemm_proj<<<gp, blk, SMEM_BYTES>>>(det16, rel16, wd16, wr16, wv16,
                                        b_det, b_rel, b_val, q16, k16, v16);

    // --- scores (NT, fp16 out)
    dim3 gs(NR / 128, ND / 256, NB);
    hgemm<false, __half><<<gs, blk, SMEM_BYTES>>>(k16, q16, s16, nullptr, nullptr, 0,
        DF, DF, (long)NR * DF, DF, (long)ND * DF, ND, (long)NR * ND);

    // --- single-pass exp + 1/rowsum (normalization folded into AV epilogue)
    softmax_exp<<<NB * NR, 256>>>(s16, 1.f / sqrtf((float)DF), inv);

    // --- rel_add = (e @ v) * inv   (NN, fp32 out)
    dim3 ga(NR / 128, DF / 256, NB);
    hgemm<true, float><<<ga, blk, SMEM_BYTES>>>(s16, v16, add, nullptr, inv, NR,
        ND, ND, (long)NR * ND, DF, (long)ND * DF, DF, (long)NR * DF);

    // --- residual + LayerNorm -> out[Nd*B*D + ...]
    residual_ln<<<NB * NR, 128>>>(add, rel_in, gamma, beta,
                                  out + (size_t)ND * NB * DM);
}

// round 9
// speedup vs baseline: 6.3664x; 1.0553x over previous
#include <cuda_runtime.h>
#include <cuda_fp16.h>
#include <cstdint>
#include <math.h>

// ---------------------------------------------------------------------------
// InteractionLayer via fp16 mma.sync m16n8k16 + 4-stage cp.async + ldmatrix
// (arch-portable PTX; harness targets plain sm_103 — no 'a' features).
// GEMM: CTA 128x256, 8 warps (2x4) of 64x64, BK=32, 4-stage cp.async,
// single __syncthreads per slab.
// R9: fix R8 compile error (arg list); single cvt launch, fp16 rel_add,
// fork-join stream overlap (pass-through memcpy + V projection hidden behind
// Q/K projections + scores + softmax).
// ---------------------------------------------------------------------------

#define ND 2048
#define NR 2048
#define NB 8
#define DM 512
#define DF 512

// scratch (no cudaMalloc allowed)
__device__ __align__(16) __half g_det16[(size_t)ND * NB * DM];
__device__ __align__(16) __half g_rel16[(size_t)NR * NB * DM];
__device__ __align__(16) __half g_wd16[(size_t)DF * DM];
__device__ __align__(16) __half g_wr16[(size_t)DF * DM];
__device__ __align__(16) __half g_wv16[(size_t)DF * DM];
__device__ __align__(16) __half g_q16[(size_t)NB * ND * DF];
__device__ __align__(16) __half g_k16[(size_t)NB * NR * DF];
__device__ __align__(16) __half g_v16[(size_t)NB * ND * DF];
__device__ __align__(16) __half g_s16[(size_t)NB * NR * ND];   // scores, then e
__device__ __align__(16) __half g_add16[(size_t)NB * NR * DF]; // rel_add (fp16)
__device__ float g_inv[(size_t)NB * NR];

__device__ __forceinline__ uint32_t smem_u32(const void* p) {
    uint32_t a;
    asm("{ .reg .u64 t; cvta.to.shared.u64 t, %1; cvt.u32.u64 %0, t; }" : "=r"(a) : "l"(p));
    return a;
}
__device__ __forceinline__ void cp16(uint32_t dst, const void* src) {
    asm volatile("cp.async.ca.shared.global [%0], [%1], 16;" :: "r"(dst), "l"(src) : "memory");
}
#define CP_COMMIT() asm volatile("cp.async.commit_group;" ::: "memory")

__device__ __forceinline__ void ldsm4(uint32_t* r, uint32_t a) {
    asm volatile("ldmatrix.sync.aligned.m8n8.x4.shared.b16 {%0,%1,%2,%3}, [%4];"
                 : "=r"(r[0]), "=r"(r[1]), "=r"(r[2]), "=r"(r[3]) : "r"(a));
}
__device__ __forceinline__ void ldsm4t(uint32_t* r, uint32_t a) {
    asm volatile("ldmatrix.sync.aligned.m8n8.x4.trans.shared.b16 {%0,%1,%2,%3}, [%4];"
                 : "=r"(r[0]), "=r"(r[1]), "=r"(r[2]), "=r"(r[3]) : "r"(a));
}

// smem halves per buffer (30720 B): As 128x40 (10240 B), Bs 20480 B
// (NT: 256x40; NN: 32x264). FOUR buffers: 122880 B.
#define AS_STRIDE 40
#define BNT_STRIDE 40
#define BNN_STRIDE 264
#define BUF_BYTES 30720
#define NSTAGE 4
#define SMEM_BYTES (NSTAGE * BUF_BYTES)

// ---------------------------------------------------------------------------
// Core GEMM body. 256 threads, 8 warps (2x4), warp tile 64x64, CTA 128x256.
// BNN=false (NT): C[m,n] = sum_k A[m*rsA+k] * B[n*rsB+k]
// BNN=true  (NN): C[m,n] = sum_k A[m*rsA+k] * B[k*rsB+n]
// ---------------------------------------------------------------------------
template <bool BNN, typename OutT>
__device__ __forceinline__ void gemm_body(
    const __half* __restrict__ A, const __half* __restrict__ B, OutT* __restrict__ C,
    const float* __restrict__ bias, const float* __restrict__ rowScale,
    int K, long rsA, long rsB, long rsC)
{
    extern __shared__ __align__(16) char dyn[];
    const uint32_t sb = smem_u32(dyn);

    const int tid = threadIdx.x;
    const int wid = tid >> 5;
    const int lane = tid & 31;
    const int g = lane >> 2;
    const int c = lane & 3;
    const int t8 = lane >> 3;
    const int lr = lane & 7;
    const int wm = (wid >> 2) * 64;
    const int wn = (wid & 3) * 64;

    const long rowBase = (long)blockIdx.x * 128;
    const long colBase = (long)blockIdx.y * 256;

    float acc[4][8][4];
    #pragma unroll
    for (int mt = 0; mt < 4; mt++)
        #pragma unroll
        for (int nt = 0; nt < 8; nt++)
            #pragma unroll
            for (int r = 0; r < 4; r++) acc[mt][nt][r] = 0.f;

    const int NS = K / 32;

    auto issue = [&](int s) {
        const int buf = s % NSTAGE;
        const long k0 = (long)s * 32;
        const uint32_t ab = sb + buf * BUF_BYTES;
        const uint32_t bb = ab + 10240;
        #pragma unroll
        for (int i = 0; i < 2; i++) {
            const int idx = i * 256 + tid;
            const int row = idx >> 2, ch = idx & 3;
            cp16(ab + (row * AS_STRIDE + ch * 8) * 2,
                 &A[(rowBase + row) * rsA + k0 + ch * 8]);
        }
        if (BNN) {
            #pragma unroll
            for (int i = 0; i < 4; i++) {
                const int idx = i * 256 + tid;
                const int kr = idx >> 5, ch = idx & 31;
                cp16(bb + (kr * BNN_STRIDE + ch * 8) * 2,
                     &B[(k0 + kr) * rsB + colBase + ch * 8]);
            }
        } else {
            #pragma unroll
            for (int i = 0; i < 4; i++) {
                const int idx = i * 256 + tid;
                const int row = idx >> 2, ch = idx & 3;
                cp16(bb + (row * BNT_STRIDE + ch * 8) * 2,
                     &B[(colBase + row) * rsB + k0 + ch * 8]);
            }
        }
        CP_COMMIT();
    };

    issue(0);
    if (NS > 1) issue(1);
    if (NS > 2) issue(2);

    for (int s = 0; s < NS; s++) {
        if (s + 3 <= NS)
            asm volatile("cp.async.wait_group 2;" ::: "memory");
        else if (s + 2 == NS)
            asm volatile("cp.async.wait_group 1;" ::: "memory");
        else
            asm volatile("cp.async.wait_group 0;" ::: "memory");
        __syncthreads();

        const uint32_t ab = sb + (s % NSTAGE) * BUF_BYTES;
        const uint32_t bb = ab + 10240;

        #pragma unroll
        for (int kk = 0; kk < 2; kk++) {
            const int k0h = kk * 16;
            uint32_t a[4][4];
            #pragma unroll
            for (int mt = 0; mt < 4; mt++)
                ldsm4(a[mt], ab + ((wm + mt * 16 + (t8 & 1) * 8 + lr) * AS_STRIDE
                                   + k0h + (t8 >> 1) * 8) * 2);
            uint32_t b[4][4];
            #pragma unroll
            for (int np = 0; np < 4; np++) {
                if (BNN)
                    ldsm4t(b[np], bb + ((k0h + (t8 & 1) * 8 + lr) * BNN_STRIDE
                                        + wn + np * 16 + (t8 >> 1) * 8) * 2);
                else
                    ldsm4(b[np], bb + ((wn + np * 16 + (t8 >> 1) * 8 + lr) * BNT_STRIDE
                                       + k0h + (t8 & 1) * 8) * 2);
            }
            #pragma unroll
            for (int mt = 0; mt < 4; mt++)
                #pragma unroll
                for (int nt = 0; nt < 8; nt++)
                    asm volatile(
                        "mma.sync.aligned.m16n8k16.row.col.f32.f16.f16.f32 "
                        "{%0,%1,%2,%3}, {%4,%5,%6,%7}, {%8,%9}, {%0,%1,%2,%3};"
                        : "+f"(acc[mt][nt][0]), "+f"(acc[mt][nt][1]),
                          "+f"(acc[mt][nt][2]), "+f"(acc[mt][nt][3])
                        : "r"(a[mt][0]), "r"(a[mt][1]), "r"(a[mt][2]), "r"(a[mt][3]),
                          "r"(b[nt >> 1][(nt & 1) * 2]), "r"(b[nt >> 1][(nt & 1) * 2 + 1]));
        }
        if (s + 3 < NS) issue(s + 3);
    }

    // ---- epilogue
    #pragma unroll
    for (int mt = 0; mt < 4; mt++) {
        const long row0 = rowBase + wm + mt * 16 + g;
        float sc0 = 1.f, sc1 = 1.f;
        if (rowScale) {
            sc0 = rowScale[row0];
            sc1 = rowScale[row0 + 8];
        }
        #pragma unroll
        for (int nt = 0; nt < 8; nt++) {
            const long col = colBase + wn + nt * 8 + 2 * c;
            float bx = 0.f, by = 0.f;
            if (bias) { bx = bias[col]; by = bias[col + 1]; }
            float x0 = acc[mt][nt][0] * sc0 + bx, x1 = acc[mt][nt][1] * sc0 + by;
            float x2 = acc[mt][nt][2] * sc1 + bx, x3 = acc[mt][nt][3] * sc1 + by;
            if (sizeof(OutT) == 2) {
                *reinterpret_cast<__half2*>(C + row0 * rsC + col) = __floats2half2_rn(x0, x1);
                *reinterpret_cast<__half2*>(C + (row0 + 8) * rsC + col) = __floats2half2_rn(x2, x3);
            } else {
                *reinterpret_cast<float2*>((float*)C + row0 * rsC + col) = make_float2(x0, x1);
                *reinterpret_cast<float2*>((float*)C + (row0 + 8) * rsC + col) = make_float2(x2, x3);
            }
        }
    }
}

// Generic batched wrapper.
template <bool BNN, typename OutT>
__global__ __launch_bounds__(256, 1) void hgemm(
    const __half* __restrict__ A, const __half* __restrict__ B, OutT* __restrict__ C,
    const float* __restrict__ bias, const float* __restrict__ rowScale, long ssS,
    int K, long rsA, long bsA, long rsB, long bsB, long rsC, long bsC)
{
    const int bz = blockIdx.z;
    gemm_body<BNN, OutT>(A + (long)bz * bsA, B + (long)bz * bsB, C + (long)bz * bsC,
                         bias, rowScale ? rowScale + (long)bz * ssS : nullptr,
                         K, rsA, rsB, rsC);
}

// Q+K projections in one launch: z = which*NB + b; which: 0->det_q, 1->rel_k.
__global__ __launch_bounds__(256, 1) void hgemm_projqk(
    const __half* __restrict__ det16, const __half* __restrict__ rel16,
    const __half* __restrict__ wd, const __half* __restrict__ wr,
    const float* __restrict__ bd, const float* __restrict__ br,
    __half* __restrict__ q16, __half* __restrict__ k16)
{
    const int z = blockIdx.z;
    const int which = z >> 3;
    const int b = z & 7;
    const __half* A = which ? rel16 : det16;
    const __half* W = which ? wr : wd;
    const float* bias = which ? br : bd;
    __half* C = which ? k16 : q16;
    gemm_body<false, __half>(A + (long)b * DM, W, C + (long)b * ND * DF,
                             bias, nullptr, DM, (long)NB * DM, DM, DF);
}

// ---------------------------------------------------------------------------
// One launch converting all five fp32 tensors to fp16. z selects the tensor.
// ---------------------------------------------------------------------------
__global__ __launch_bounds__(256) void cvt_all(
    const float* __restrict__ det, const float* __restrict__ rel,
    const float* __restrict__ wd, const float* __restrict__ wr,
    const float* __restrict__ wv,
    __half* __restrict__ det16, __half* __restrict__ rel16,
    __half* __restrict__ wd16, __half* __restrict__ wr16, __half* __restrict__ wv16)
{
    const float* src; __half* dst; long n;
    switch (blockIdx.z) {
        case 0: src = det; dst = det16; n = (long)ND * NB * DM; break;
        case 1: src = rel; dst = rel16; n = (long)NR * NB * DM; break;
        case 2: src = wd;  dst = wd16;  n = (long)DF * DM; break;
        case 3: src = wr;  dst = wr16;  n = (long)DF * DM; break;
        default: src = wv; dst = wv16;  n = (long)DF * DM; break;
    }
    long i = ((long)blockIdx.x * blockDim.x + threadIdx.x) * 4;
    const long stride = (long)gridDim.x * blockDim.x * 4;
    for (; i < n; i += stride) {
        float4 v = *reinterpret_cast<const float4*>(src + i);
        __half2* p = reinterpret_cast<__half2*>(dst + i);
        p[0] = __floats2half2_rn(v.x, v.y);
        p[1] = __floats2half2_rn(v.z, v.w);
    }
}

// ---------------------------------------------------------------------------
// Single-pass softmax on fp16 scores (2048 cols = 256 thr x 8 vals).
// ---------------------------------------------------------------------------
__global__ __launch_bounds__(256) void softmax_exp(
    __half* __restrict__ S, float scale, float* __restrict__ inv)
{
    __half* p = S + (long)blockIdx.x * 2048;
    const int tid = threadIdx.x;
    __shared__ float red[256];

    uint4 raw = *reinterpret_cast<const uint4*>(p + tid * 8);
    const __half2* h = reinterpret_cast<const __half2*>(&raw);
    float x[8];
    #pragma unroll
    for (int i = 0; i < 4; i++) {
        float2 f = __half22float2(h[i]);
        x[2 * i] = f.x; x[2 * i + 1] = f.y;
    }

    float m = x[0];
    #pragma unroll
    for (int i = 1; i < 8; i++) m = fmaxf(m, x[i]);
    red[tid] = m; __syncthreads();
    for (int s = 128; s > 0; s >>= 1) {
        if (tid < s) red[tid] = fmaxf(red[tid], red[tid + s]);
        __syncthreads();
    }
    m = red[0];
    __syncthreads();

    float e[8], sum = 0.f;
    #pragma unroll
    for (int i = 0; i < 8; i++) {
        e[i] = __expf((x[i] - m) * scale);
        sum += e[i];
    }
    uint4 outw;
    __half2* ho = reinterpret_cast<__half2*>(&outw);
    #pragma unroll
    for (int i = 0; i < 4; i++)
        ho[i] = __floats2half2_rn(e[2 * i], e[2 * i + 1]);
    *reinterpret_cast<uint4*>(p + tid * 8) = outw;

    red[tid] = sum; __syncthreads();
    for (int s = 128; s > 0; s >>= 1) {
        if (tid < s) red[tid] += red[tid + s];
        __syncthreads();
    }
    if (tid == 0) inv[blockIdx.x] = 1.f / red[0];
}

// ---------------------------------------------------------------------------
// out[r][b][:] = LN(add16[b][r][:] + rel_in[r][b][:]) * gamma + beta
// ---------------------------------------------------------------------------
__global__ __launch_bounds__(128) void residual_ln(
    const __half* __restrict__ add, const float* __restrict__ rel_in,
    const float* __restrict__ gamma, const float* __restrict__ beta,
    float* __restrict__ out)
{
    const long idx = blockIdx.x;          // b*NR + r
    const long b = idx >> 11;
    const long r = idx & 2047;
    const int tid = threadIdx.x;
    const int f = tid * 4;

    uint2 araw = *reinterpret_cast<const uint2*>(&add[idx * DM + f]);
    const __half2* ah = reinterpret_cast<const __half2*>(&araw);
    float2 a01 = __half22float2(ah[0]);
    float2 a23 = __half22float2(ah[1]);
    const float4 r4 = *reinterpret_cast<const float4*>(&rel_in[(r * NB + b) * DM + f]);
    float x0 = a01.x + r4.x, x1 = a01.y + r4.y, x2 = a23.x + r4.z, x3 = a23.y + r4.w;

    float sum = x0 + x1 + x2 + x3;
    float ssq = x0 * x0 + x1 * x1 + x2 * x2 + x3 * x3;
    #pragma unroll
    for (int o = 16; o > 0; o >>= 1) {
        sum += __shfl_xor_sync(0xFFFFFFFFu, sum, o);
        ssq += __shfl_xor_sync(0xFFFFFFFFu, ssq, o);
    }
    __shared__ float s1[4], s2[4];
    const int w = tid >> 5;
    if ((tid & 31) == 0) { s1[w] = sum; s2[w] = ssq; }
    __syncthreads();
    sum = s1[0] + s1[1] + s1[2] + s1[3];
    ssq = s2[0] + s2[1] + s2[2] + s2[3];

    const float mean = sum * (1.f / DM);
    const float var = ssq * (1.f / DM) - mean * mean;
    const float rstd = rsqrtf(var + 1e-5f);

    const float4 g4 = *reinterpret_cast<const float4*>(&gamma[f]);
    const float4 be4 = *reinterpret_cast<const float4*>(&beta[f]);
    float4 o4;
    o4.x = (x0 - mean) * rstd * g4.x + be4.x;
    o4.y = (x1 - mean) * rstd * g4.y + be4.y;
    o4.z = (x2 - mean) * rstd * g4.z + be4.z;
    o4.w = (x3 - mean) * rstd * g4.w + be4.w;
    *reinterpret_cast<float4*>(&out[(r * NB + b) * DM + f]) = o4;
}

// ---------------------------------------------------------------------------
extern "C" void kernel_launch(void* const* d_in, const int* in_sizes, int n_in,
                              void* d_out, int out_size)
{
    const float* det_in = (const float*)d_in[0];
    const float* rel_in = (const float*)d_in[1];
    const float* W_det  = (const float*)d_in[2];
    const float* b_det  = (const float*)d_in[3];
    const float* W_rel  = (const float*)d_in[4];
    const float* b_rel  = (const float*)d_in[5];
    const float* W_val  = (const float*)d_in[6];
    const float* b_val  = (const float*)d_in[7];
    const float* gamma  = (const float*)d_in[8];
    const float* beta   = (const float*)d_in[9];
    float* out = (float*)d_out;

    __half *det16, *rel16, *wd16, *wr16, *wv16, *q16, *k16, *v16, *s16, *add16;
    float *inv;
    cudaGetSymbolAddress((void**)&det16, g_det16);
    cudaGetSymbolAddress((void**)&rel16, g_rel16);
    cudaGetSymbolAddress((void**)&wd16, g_wd16);
    cudaGetSymbolAddress((void**)&wr16, g_wr16);
    cudaGetSymbolAddress((void**)&wv16, g_wv16);
    cudaGetSymbolAddress((void**)&q16, g_q16);
    cudaGetSymbolAddress((void**)&k16, g_k16);
    cudaGetSymbolAddress((void**)&v16, g_v16);
    cudaGetSymbolAddress((void**)&s16, g_s16);
    cudaGetSymbolAddress((void**)&add16, g_add16);
    cudaGetSymbolAddress((void**)&inv, g_inv);

    cudaFuncSetAttribute(hgemm_projqk, cudaFuncAttributeMaxDynamicSharedMemorySize, SMEM_BYTES);
    cudaFuncSetAttribute(hgemm<false, __half>, cudaFuncAttributeMaxDynamicSharedMemorySize, SMEM_BYTES);
    cudaFuncSetAttribute(hgemm<true, __half>,  cudaFuncAttributeMaxDynamicSharedMemorySize, SMEM_BYTES);

    // Side stream + events for fork-join overlap (created once, outside capture;
    // the captured work is identical on every call).
    static cudaStream_t s2 = nullptr;
    static cudaEvent_t evCvt = nullptr, evV = nullptr;
    if (!s2) {
        cudaStreamCreateWithFlags(&s2, cudaStreamNonBlocking);
        cudaEventCreateWithFlags(&evCvt, cudaEventDisableTiming);
        cudaEventCreateWithFlags(&evV, cudaEventDisableTiming);
    }

    dim3 blk(256);

    // --- all fp32->fp16 conversions in ONE launch
    cvt_all<<<dim3(2048, 1, 5), blk>>>(det_in, rel_in, W_det, W_rel, W_val,
                                       det16, rel16, wd16, wr16, wv16);
    cudaEventRecord(evCvt, 0);

    // --- side stream: pass-through copy + V projection (hidden behind scores)
    cudaStreamWaitEvent(s2, evCvt, 0);
    cudaMemcpyAsync(out, det_in, (size_t)ND * NB * DM * sizeof(float),
                    cudaMemcpyDeviceToDevice, s2);
    dim3 gv(ND / 128, DF / 256, NB);
    hgemm<false, __half><<<gv, blk, SMEM_BYTES, s2>>>(det16, wv16, v16, b_val,
        nullptr, (long)0, DM,
        (long)NB * DM, (long)DM, (long)DM, (long)0, (long)DF, (long)ND * DF);
    cudaEventRecord(evV, s2);

    // --- main stream: Q+K projections (one launch, 512 CTAs)
    dim3 gqk(ND / 128, DF / 256, 2 * NB);
    hgemm_projqk<<<gqk, blk, SMEM_BYTES>>>(det16, rel16, wd16, wr16,
                                           b_det, b_rel, q16, k16);

    // --- scores (NT, fp16 out)
    dim3 gs(NR / 128, ND / 256, NB);
    hgemm<false, __half><<<gs, blk, SMEM_BYTES>>>(k16, q16, s16, nullptr, nullptr,
        (long)0, DF,
        (long)DF, (long)NR * DF, (long)DF, (long)ND * DF, (long)ND, (long)NR * ND);

    // --- single-pass exp + 1/rowsum
    softmax_exp<<<NB * NR, 256>>>(s16, 1.f / sqrtf((float)DF), inv);

    // --- join: AV needs v16 from the side stream
    cudaStreamWaitEvent(0, evV, 0);

    // --- rel_add = (e @ v) * inv   (NN, fp16 out)
    dim3 ga(NR / 128, DF / 256, NB);
    hgemm<true, __half><<<ga, blk, SMEM_BYTES>>>(s16, v16, add16, nullptr, inv,
        (long)NR, ND,
        (long)ND, (long)NR * ND, (long)DF, (long)ND * DF, (long)DF, (long)NR * DF);

    // --- residual + LayerNorm -> out[Nd*B*D + ...]
    residual_ln<<<NB * NR, 128>>>(add16, rel_in, gamma, beta,
                                  out + (size_t)ND * NB * DM);
}

// round 10
// speedup vs baseline: 7.0297x; 1.1042x over previous
#include <cuda_runtime.h>
#include <cuda_fp16.h>
#include <cstdint>
#include <math.h>

// ---------------------------------------------------------------------------
// InteractionLayer via fp16 mma.sync m16n8k16 + 4-stage cp.async + ldmatrix
// (arch-portable PTX; harness targets plain sm_103 — no 'a' features).
// GEMM: CTA 128x256, 8 warps (2x4) of 64x64, BK=32, 4-stage cp.async.
// R10: softmax fused into GEMM epilogues — scores epilogue emits
// exp(acc*scale) fp16 + deterministic per-(row,colBlk) partial sums;
// AV epilogue divides by the summed partials. Softmax kernel deleted.
// ---------------------------------------------------------------------------

#define ND 2048
#define NR 2048
#define NB 8
#define DM 512
#define DF 512
#define PSUM_BLKS 8   // scores gridDim.y = ND/256

// scratch (no cudaMalloc allowed)
__device__ __align__(16) __half g_det16[(size_t)ND * NB * DM];
__device__ __align__(16) __half g_rel16[(size_t)NR * NB * DM];
__device__ __align__(16) __half g_wd16[(size_t)DF * DM];
__device__ __align__(16) __half g_wr16[(size_t)DF * DM];
__device__ __align__(16) __half g_wv16[(size_t)DF * DM];
__device__ __align__(16) __half g_q16[(size_t)NB * ND * DF];
__device__ __align__(16) __half g_k16[(size_t)NB * NR * DF];
__device__ __align__(16) __half g_v16[(size_t)NB * ND * DF];
__device__ __align__(16) __half g_s16[(size_t)NB * NR * ND];    // exp weights
__device__ __align__(16) __half g_add16[(size_t)NB * NR * DF];  // rel_add
__device__ __align__(16) float  g_psum[(size_t)NB * PSUM_BLKS * NR]; // partial row sums

__device__ __forceinline__ uint32_t smem_u32(const void* p) {
    uint32_t a;
    asm("{ .reg .u64 t; cvta.to.shared.u64 t, %1; cvt.u32.u64 %0, t; }" : "=r"(a) : "l"(p));
    return a;
}
__device__ __forceinline__ void cp16(uint32_t dst, const void* src) {
    asm volatile("cp.async.cg.shared.global [%0], [%1], 16;" :: "r"(dst), "l"(src) : "memory");
}
#define CP_COMMIT() asm volatile("cp.async.commit_group;" ::: "memory")

__device__ __forceinline__ void ldsm4(uint32_t* r, uint32_t a) {
    asm volatile("ldmatrix.sync.aligned.m8n8.x4.shared.b16 {%0,%1,%2,%3}, [%4];"
                 : "=r"(r[0]), "=r"(r[1]), "=r"(r[2]), "=r"(r[3]) : "r"(a));
}
__device__ __forceinline__ void ldsm4t(uint32_t* r, uint32_t a) {
    asm volatile("ldmatrix.sync.aligned.m8n8.x4.trans.shared.b16 {%0,%1,%2,%3}, [%4];"
                 : "=r"(r[0]), "=r"(r[1]), "=r"(r[2]), "=r"(r[3]) : "r"(a));
}
__device__ __forceinline__ float fex2(float x) {      // 2^x, hardware approx
    float r;
    asm("ex2.approx.f32 %0, %1;" : "=f"(r) : "f"(x));
    return r;
}

// smem halves per buffer (30720 B): As 128x40 (10240 B), Bs 20480 B
// (NT: 256x40; NN: 32x264). FOUR buffers: 122880 B.
#define AS_STRIDE 40
#define BNT_STRIDE 40
#define BNN_STRIDE 264
#define BUF_BYTES 30720
#define NSTAGE 4
#define SMEM_BYTES (NSTAGE * BUF_BYTES)

// ---------------------------------------------------------------------------
// Core GEMM body. 256 threads, 8 warps (2x4), warp tile 64x64, CTA 128x256.
// BNN=false (NT): C[m,n] = sum_k A[m*rsA+k] * B[n*rsB+k]
// BNN=true  (NN): C[m,n] = sum_k A[m*rsA+k] * B[k*rsB+n]
// EPI: 0 = bias add; 1 = exp(acc*escale) + partial row sums into aux
//      (aux[colBlk * (gridDim.x*128) + row], colBlk = blockIdx.y);
//      2 = multiply by 1/(sum of PSUM_BLKS partials from aux).
// aux is pre-offset for the batch by the caller.
// ---------------------------------------------------------------------------
template <bool BNN, int EPI, typename OutT>
__device__ __forceinline__ void gemm_body(
    const __half* __restrict__ A, const __half* __restrict__ B, OutT* __restrict__ C,
    const float* __restrict__ bias, float* __restrict__ aux, float escale,
    int K, long rsA, long rsB, long rsC)
{
    extern __shared__ __align__(16) char dyn[];
    const uint32_t sb = smem_u32(dyn);

    const int tid = threadIdx.x;
    const int wid = tid >> 5;
    const int lane = tid & 31;
    const int g = lane >> 2;
    const int c = lane & 3;
    const int t8 = lane >> 3;
    const int lr = lane & 7;
    const int wm = (wid >> 2) * 64;
    const int wn = (wid & 3) * 64;

    const long rowBase = (long)blockIdx.x * 128;
    const long colBase = (long)blockIdx.y * 256;

    float acc[4][8][4];
    #pragma unroll
    for (int mt = 0; mt < 4; mt++)
        #pragma unroll
        for (int nt = 0; nt < 8; nt++)
            #pragma unroll
            for (int r = 0; r < 4; r++) acc[mt][nt][r] = 0.f;

    const int NS = K / 32;

    auto issue = [&](int s) {
        const int buf = s % NSTAGE;
        const long k0 = (long)s * 32;
        const uint32_t ab = sb + buf * BUF_BYTES;
        const uint32_t bb = ab + 10240;
        #pragma unroll
        for (int i = 0; i < 2; i++) {
            const int idx = i * 256 + tid;
            const int row = idx >> 2, ch = idx & 3;
            cp16(ab + (row * AS_STRIDE + ch * 8) * 2,
                 &A[(rowBase + row) * rsA + k0 + ch * 8]);
        }
        if (BNN) {
            #pragma unroll
            for (int i = 0; i < 4; i++) {
                const int idx = i * 256 + tid;
                const int kr = idx >> 5, ch = idx & 31;
                cp16(bb + (kr * BNN_STRIDE + ch * 8) * 2,
                     &B[(k0 + kr) * rsB + colBase + ch * 8]);
            }
        } else {
            #pragma unroll
            for (int i = 0; i < 4; i++) {
                const int idx = i * 256 + tid;
                const int row = idx >> 2, ch = idx & 3;
                cp16(bb + (row * BNT_STRIDE + ch * 8) * 2,
                     &B[(colBase + row) * rsB + k0 + ch * 8]);
            }
        }
        CP_COMMIT();
    };

    issue(0);
    if (NS > 1) issue(1);
    if (NS > 2) issue(2);

    for (int s = 0; s < NS; s++) {
        if (s + 3 <= NS)
            asm volatile("cp.async.wait_group 2;" ::: "memory");
        else if (s + 2 == NS)
            asm volatile("cp.async.wait_group 1;" ::: "memory");
        else
            asm volatile("cp.async.wait_group 0;" ::: "memory");
        __syncthreads();

        const uint32_t ab = sb + (s % NSTAGE) * BUF_BYTES;
        const uint32_t bb = ab + 10240;

        #pragma unroll
        for (int kk = 0; kk < 2; kk++) {
            const int k0h = kk * 16;
            uint32_t a[4][4];
            #pragma unroll
            for (int mt = 0; mt < 4; mt++)
                ldsm4(a[mt], ab + ((wm + mt * 16 + (t8 & 1) * 8 + lr) * AS_STRIDE
                                   + k0h + (t8 >> 1) * 8) * 2);
            uint32_t b[4][4];
            #pragma unroll
            for (int np = 0; np < 4; np++) {
                if (BNN)
                    ldsm4t(b[np], bb + ((k0h + (t8 & 1) * 8 + lr) * BNN_STRIDE
                                        + wn + np * 16 + (t8 >> 1) * 8) * 2);
                else
                    ldsm4(b[np], bb + ((wn + np * 16 + (t8 >> 1) * 8 + lr) * BNT_STRIDE
                                       + k0h + (t8 & 1) * 8) * 2);
            }
            #pragma unroll
            for (int mt = 0; mt < 4; mt++)
                #pragma unroll
                for (int nt = 0; nt < 8; nt++)
                    asm volatile(
                        "mma.sync.aligned.m16n8k16.row.col.f32.f16.f16.f32 "
                        "{%0,%1,%2,%3}, {%4,%5,%6,%7}, {%8,%9}, {%0,%1,%2,%3};"
                        : "+f"(acc[mt][nt][0]), "+f"(acc[mt][nt][1]),
                          "+f"(acc[mt][nt][2]), "+f"(acc[mt][nt][3])
                        : "r"(a[mt][0]), "r"(a[mt][1]), "r"(a[mt][2]), "r"(a[mt][3]),
                          "r"(b[nt >> 1][(nt & 1) * 2]), "r"(b[nt >> 1][(nt & 1) * 2 + 1]));
        }
        if (s + 3 < NS) issue(s + 3);
    }

    const long nRowsTot = (long)gridDim.x * 128;   // rows of C (psum leading dim)

    // ---- epilogue
    float rsum[4][2];   // EPI==1: per-mt partial row sums (this lane's 16 cols)
    #pragma unroll
    for (int mt = 0; mt < 4; mt++) { rsum[mt][0] = 0.f; rsum[mt][1] = 0.f; }

    #pragma unroll
    for (int mt = 0; mt < 4; mt++) {
        const long row0 = rowBase + wm + mt * 16 + g;
        float sc0 = 1.f, sc1 = 1.f;
        if (EPI == 2) {
            float s0 = 0.f, s1 = 0.f;
            #pragma unroll
            for (int k = 0; k < PSUM_BLKS; k++) {
                s0 += aux[(long)k * nRowsTot + row0];
                s1 += aux[(long)k * nRowsTot + row0 + 8];
            }
            sc0 = 1.f / s0;
            sc1 = 1.f / s1;
        }
        #pragma unroll
        for (int nt = 0; nt < 8; nt++) {
            const long col = colBase + wn + nt * 8 + 2 * c;
            float x0 = acc[mt][nt][0], x1 = acc[mt][nt][1];
            float x2 = acc[mt][nt][2], x3 = acc[mt][nt][3];
            if (EPI == 0) {
                float bx = 0.f, by = 0.f;
                if (bias) { bx = bias[col]; by = bias[col + 1]; }
                x0 += bx; x1 += by; x2 += bx; x3 += by;
            } else if (EPI == 1) {
                x0 = fex2(x0 * escale); x1 = fex2(x1 * escale);
                x2 = fex2(x2 * escale); x3 = fex2(x3 * escale);
                rsum[mt][0] += x0 + x1;
                rsum[mt][1] += x2 + x3;
            } else {
                x0 *= sc0; x1 *= sc0; x2 *= sc1; x3 *= sc1;
            }
            if (sizeof(OutT) == 2) {
                *reinterpret_cast<__half2*>(C + row0 * rsC + col) = __floats2half2_rn(x0, x1);
                *reinterpret_cast<__half2*>(C + (row0 + 8) * rsC + col) = __floats2half2_rn(x2, x3);
            } else {
                *reinterpret_cast<float2*>((float*)C + row0 * rsC + col) = make_float2(x0, x1);
                *reinterpret_cast<float2*>((float*)C + (row0 + 8) * rsC + col) = make_float2(x2, x3);
            }
        }
    }

    if (EPI == 1) {
        // reduce this lane's partials across the 4 c-lanes sharing a row
        float* sred = reinterpret_cast<float*>(dyn);   // [128 rows][4 n-warps]
        __syncthreads();   // mainloop smem reads finished everywhere
        #pragma unroll
        for (int mt = 0; mt < 4; mt++) {
            float v0 = rsum[mt][0], v1 = rsum[mt][1];
            v0 += __shfl_xor_sync(0xFFFFFFFFu, v0, 1);
            v0 += __shfl_xor_sync(0xFFFFFFFFu, v0, 2);
            v1 += __shfl_xor_sync(0xFFFFFFFFu, v1, 1);
            v1 += __shfl_xor_sync(0xFFFFFFFFu, v1, 2);
            if (c == 0) {
                const int rl = wm + mt * 16 + g;
                sred[rl * 4 + (wid & 3)] = v0;
                sred[(rl + 8) * 4 + (wid & 3)] = v1;
            }
        }
        __syncthreads();
        if (tid < 128) {
            const float s = sred[tid * 4] + sred[tid * 4 + 1]
                          + sred[tid * 4 + 2] + sred[tid * 4 + 3];
            aux[(long)blockIdx.y * nRowsTot + rowBase + tid] = s;
        }
    }
}

// Generic batched wrapper.
template <bool BNN, int EPI, typename OutT>
__global__ __launch_bounds__(256, 1) void hgemm(
    const __half* __restrict__ A, const __half* __restrict__ B, OutT* __restrict__ C,
    const float* __restrict__ bias, float* __restrict__ aux, long auxStride,
    float escale, int K,
    long rsA, long bsA, long rsB, long bsB, long rsC, long bsC)
{
    const int bz = blockIdx.z;
    gemm_body<BNN, EPI, OutT>(A + (long)bz * bsA, B + (long)bz * bsB,
                              C + (long)bz * bsC, bias,
                              aux ? aux + (long)bz * auxStride : nullptr,
                              escale, K, rsA, rsB, rsC);
}

// Q+K projections in one launch: z = which*NB + b; which: 0->det_q, 1->rel_k.
__global__ __launch_bounds__(256, 1) void hgemm_projqk(
    const __half* __restrict__ det16, const __half* __restrict__ rel16,
    const __half* __restrict__ wd, const __half* __restrict__ wr,
    const float* __restrict__ bd, const float* __restrict__ br,
    __half* __restrict__ q16, __half* __restrict__ k16)
{
    const int z = blockIdx.z;
    const int which = z >> 3;
    const int b = z & 7;
    const __half* A = which ? rel16 : det16;
    const __half* W = which ? wr : wd;
    const float* bias = which ? br : bd;
    __half* C = which ? k16 : q16;
    gemm_body<false, 0, __half>(A + (long)b * DM, W, C + (long)b * ND * DF,
                                bias, nullptr, 0.f, DM, (long)NB * DM, DM, DF);
}

// ---------------------------------------------------------------------------
// One launch converting all five fp32 tensors to fp16. z selects the tensor.
// ---------------------------------------------------------------------------
__global__ __launch_bounds__(256) void cvt_all(
    const float* __restrict__ det, const float* __restrict__ rel,
    const float* __restrict__ wd, const float* __restrict__ wr,
    const float* __restrict__ wv,
    __half* __restrict__ det16, __half* __restrict__ rel16,
    __half* __restrict__ wd16, __half* __restrict__ wr16, __half* __restrict__ wv16)
{
    const float* src; __half* dst; long n;
    switch (blockIdx.z) {
        case 0: src = det; dst = det16; n = (long)ND * NB * DM; break;
        case 1: src = rel; dst = rel16; n = (long)NR * NB * DM; break;
        case 2: src = wd;  dst = wd16;  n = (long)DF * DM; break;
        case 3: src = wr;  dst = wr16;  n = (long)DF * DM; break;
        default: src = wv; dst = wv16;  n = (long)DF * DM; break;
    }
    long i = ((long)blockIdx.x * blockDim.x + threadIdx.x) * 4;
    const long stride = (long)gridDim.x * blockDim.x * 4;
    for (; i < n; i += stride) {
        float4 v = *reinterpret_cast<const float4*>(src + i);
        __half2* p = reinterpret_cast<__half2*>(dst + i);
        p[0] = __floats2half2_rn(v.x, v.y);
        p[1] = __floats2half2_rn(v.z, v.w);
    }
}

// ---------------------------------------------------------------------------
// out[r][b][:] = LN(add16[b][r][:] + rel_in[r][b][:]) * gamma + beta
// ---------------------------------------------------------------------------
__global__ __launch_bounds__(128) void residual_ln(
    const __half* __restrict__ add, const float* __restrict__ rel_in,
    const float* __restrict__ gamma, const float* __restrict__ beta,
    float* __restrict__ out)
{
    const long idx = blockIdx.x;          // b*NR + r
    const long b = idx >> 11;
    const long r = idx & 2047;
    const int tid = threadIdx.x;
    const int f = tid * 4;

    uint2 araw = *reinterpret_cast<const uint2*>(&add[idx * DM + f]);
    const __half2* ah = reinterpret_cast<const __half2*>(&araw);
    float2 a01 = __half22float2(ah[0]);
    float2 a23 = __half22float2(ah[1]);
    const float4 r4 = *reinterpret_cast<const float4*>(&rel_in[(r * NB + b) * DM + f]);
    float x0 = a01.x + r4.x, x1 = a01.y + r4.y, x2 = a23.x + r4.z, x3 = a23.y + r4.w;

    float sum = x0 + x1 + x2 + x3;
    float ssq = x0 * x0 + x1 * x1 + x2 * x2 + x3 * x3;
    #pragma unroll
    for (int o = 16; o > 0; o >>= 1) {
        sum += __shfl_xor_sync(0xFFFFFFFFu, sum, o);
        ssq += __shfl_xor_sync(0xFFFFFFFFu, ssq, o);
    }
    __shared__ float s1[4], s2[4];
    const int w = tid >> 5;
    if ((tid & 31) == 0) { s1[w] = sum; s2[w] = ssq; }
    __syncthreads();
    sum = s1[0] + s1[1] + s1[2] + s1[3];
    ssq = s2[0] + s2[1] + s2[2] + s2[3];

    const float mean = sum * (1.f / DM);
    const float var = ssq * (1.f / DM) - mean * mean;
    const float rstd = rsqrtf(var + 1e-5f);

    const float4 g4 = *reinterpret_cast<const float4*>(&gamma[f]);
    const float4 be4 = *reinterpret_cast<const float4*>(&beta[f]);
    float4 o4;
    o4.x = (x0 - mean) * rstd * g4.x + be4.x;
    o4.y = (x1 - mean) * rstd * g4.y + be4.y;
    o4.z = (x2 - mean) * rstd * g4.z + be4.z;
    o4.w = (x3 - mean) * rstd * g4.w + be4.w;
    *reinterpret_cast<float4*>(&out[(r * NB + b) * DM + f]) = o4;
}

// ---------------------------------------------------------------------------
extern "C" void kernel_launch(void* const* d_in, const int* in_sizes, int n_in,
                              void* d_out, int out_size)
{
    const float* det_in = (const float*)d_in[0];
    const float* rel_in = (const float*)d_in[1];
    const float* W_det  = (const float*)d_in[2];
    const float* b_det  = (const float*)d_in[3];
    const float* W_rel  = (const float*)d_in[4];
    const float* b_rel  = (const float*)d_in[5];
    const float* W_val  = (const float*)d_in[6];
    const float* b_val  = (const float*)d_in[7];
    const float* gamma  = (const float*)d_in[8];
    const float* beta   = (const float*)d_in[9];
    float* out = (float*)d_out;

    __half *det16, *rel16, *wd16, *wr16, *wv16, *q16, *k16, *v16, *s16, *add16;
    float *psum;
    cudaGetSymbolAddress((void**)&det16, g_det16);
    cudaGetSymbolAddress((void**)&rel16, g_rel16);
    cudaGetSymbolAddress((void**)&wd16, g_wd16);
    cudaGetSymbolAddress((void**)&wr16, g_wr16);
    cudaGetSymbolAddress((void**)&wv16, g_wv16);
    cudaGetSymbolAddress((void**)&q16, g_q16);
    cudaGetSymbolAddress((void**)&k16, g_k16);
    cudaGetSymbolAddress((void**)&v16, g_v16);
    cudaGetSymbolAddress((void**)&s16, g_s16);
    cudaGetSymbolAddress((void**)&add16, g_add16);
    cudaGetSymbolAddress((void**)&psum, g_psum);

    cudaFuncSetAttribute(hgemm_projqk, cudaFuncAttributeMaxDynamicSharedMemorySize, SMEM_BYTES);
    cudaFuncSetAttribute(hgemm<false, 0, __half>, cudaFuncAttributeMaxDynamicSharedMemorySize, SMEM_BYTES);
    cudaFuncSetAttribute(hgemm<false, 1, __half>, cudaFuncAttributeMaxDynamicSharedMemorySize, SMEM_BYTES);
    cudaFuncSetAttribute(hgemm<true, 2, __half>,  cudaFuncAttributeMaxDynamicSharedMemorySize, SMEM_BYTES);

    // Side stream + events (created once, outside capture).
    static cudaStream_t s2 = nullptr;
    static cudaEvent_t evCvt = nullptr, evV = nullptr;
    if (!s2) {
        cudaStreamCreateWithFlags(&s2, cudaStreamNonBlocking);
        cudaEventCreateWithFlags(&evCvt, cudaEventDisableTiming);
        cudaEventCreateWithFlags(&evV, cudaEventDisableTiming);
    }

    dim3 blk(256);

    // --- all fp32->fp16 conversions in ONE launch
    cvt_all<<<dim3(2048, 1, 5), blk>>>(det_in, rel_in, W_det, W_rel, W_val,
                                       det16, rel16, wd16, wr16, wv16);
    cudaEventRecord(evCvt, 0);

    // --- side stream: pass-through copy + V projection
    cudaStreamWaitEvent(s2, evCvt, 0);
    cudaMemcpyAsync(out, det_in, (size_t)ND * NB * DM * sizeof(float),
                    cudaMemcpyDeviceToDevice, s2);
    dim3 gv(ND / 128, DF / 256, NB);
    hgemm<false, 0, __half><<<gv, blk, SMEM_BYTES, s2>>>(
        det16, wv16, v16, b_val, nullptr, 0L, 0.f, DM,
        (long)NB * DM, (long)DM, (long)DM, 0L, (long)DF, (long)ND * DF);
    cudaEventRecord(evV, s2);

    // --- main stream: Q+K projections (one launch, 512 CTAs)
    dim3 gqk(ND / 128, DF / 256, 2 * NB);
    hgemm_projqk<<<gqk, blk, SMEM_BYTES>>>(det16, rel16, wd16, wr16,
                                           b_det, b_rel, q16, k16);

    // --- scores (NT) with fused exp + partial row sums
    const float scl2 = (1.f / sqrtf((float)DF)) * 1.44269504f;  // log2(e)/sqrt(F)
    dim3 gs(NR / 128, ND / 256, NB);
    hgemm<false, 1, __half><<<gs, blk, SMEM_BYTES>>>(
        k16, q16, s16, nullptr, psum, (long)PSUM_BLKS * NR, scl2, DF,
        (long)DF, (long)NR * DF, (long)DF, (long)ND * DF, (long)ND, (long)NR * ND);

    // --- join: AV needs v16 from the side stream
    cudaStreamWaitEvent(0, evV, 0);

    // --- rel_add = (e @ v) / rowsum   (NN, fp16 out, fused normalization)
    dim3 ga(NR / 128, DF / 256, NB);
    hgemm<true, 2, __half><<<ga, blk, SMEM_BYTES>>>(
        s16, v16, add16, nullptr, psum, (long)PSUM_BLKS * NR, 0.f, ND,
        (long)ND, (long)NR * ND, (long)DF, (long)ND * DF, (long)DF, (long)NR * DF);

    // --- residual + LayerNorm -> out[Nd*B*D + ...]
    residual_ln<<<NB * NR, 128>>>(add16, rel_in, gamma, beta,
                                  out + (size_t)ND * NB * DM);
}